// round 1
// baseline (speedup 1.0000x reference)
#include <cuda_runtime.h>
#include <cuda_bf16.h>
#include <math.h>

// Problem constants
#define BB 4
#define LL 2048
#define GG 2
#define DD 2048
#define HH 16
#define DE 64
#define EE 1024          // H*De
#define NN 32768
#define MM (BB*LL)       // 8192 tokens
#define NC 6144          // G*D + D combined GEMM columns
#define GD (GG*DD)       // 4096
#define PAD 9            // (K-1)*DIL

// ---------------- scratch (static device globals; no allocation) ----------------
__device__ float g_emb[MM * EE];          // 33.5 MB
__device__ float g_C[(size_t)MM * NC];    // 201 MB: cols [0,4096)=keyp, [4096,6144)=vproj
__device__ float g_value[(size_t)MM * GD];// 134 MB
__device__ float g_xnorm[(size_t)MM * GD];// 134 MB

// ---------------- 1) gather embeddings ----------------
__global__ void gather_kernel(const int* __restrict__ ids,
                              const float* __restrict__ table) {
    int f = blockIdx.x * blockDim.x + threadIdx.x;   // float4 index, total MM*256
    int m  = f >> 8;          // token
    int e4 = f & 255;         // float4 within 1024-float row
    int h  = e4 >> 4;         // 16 float4 per head slot
    int j  = e4 & 15;
    int row = ids[m * HH + h] + h * NN;
    const float4* t4 = (const float4*)table;
    ((float4*)g_emb)[(size_t)m * 256 + e4] = t4[(size_t)row * 16 + j];
}

// ---------------- 2) fused NT GEMM: C[m,n] = sum_k emb[m,k]*W[n,k] ----------------
// W rows: n in [0,4096): Wk flattened (g*D+d, E). n in [4096,6144): Wv (d, E).
__global__ __launch_bounds__(256)
void gemm_kernel(const float* __restrict__ Wk, const float* __restrict__ Wv) {
    __shared__ float As[16][128];
    __shared__ float Bs[16][128];
    const int K = EE;
    int m0 = blockIdx.y * 128;
    int n0 = blockIdx.x * 128;
    const float* Bbase = (n0 < GD) ? (Wk + (size_t)n0 * K)
                                   : (Wv + (size_t)(n0 - GD) * K);
    int tid = threadIdx.x;
    int tm = (tid >> 4) * 8;
    int tn = (tid & 15) * 8;

    float acc[8][8];
#pragma unroll
    for (int i = 0; i < 8; i++)
#pragma unroll
        for (int j = 0; j < 8; j++) acc[i][j] = 0.f;

    for (int k0 = 0; k0 < K; k0 += 16) {
#pragma unroll
        for (int q = 0; q < 2; q++) {
            int li = tid * 2 + q;          // 0..511
            int mm = li >> 2;
            int kq = (li & 3) * 4;
            float4 va = *(const float4*)(g_emb + (size_t)(m0 + mm) * K + k0 + kq);
            As[kq + 0][mm] = va.x; As[kq + 1][mm] = va.y;
            As[kq + 2][mm] = va.z; As[kq + 3][mm] = va.w;
            float4 vb = *(const float4*)(Bbase + (size_t)mm * K + k0 + kq);
            Bs[kq + 0][mm] = vb.x; Bs[kq + 1][mm] = vb.y;
            Bs[kq + 2][mm] = vb.z; Bs[kq + 3][mm] = vb.w;
        }
        __syncthreads();
#pragma unroll
        for (int kk = 0; kk < 16; kk++) {
            float a[8], b[8];
            *(float4*)(a)     = *(const float4*)&As[kk][tm];
            *(float4*)(a + 4) = *(const float4*)&As[kk][tm + 4];
            *(float4*)(b)     = *(const float4*)&Bs[kk][tn];
            *(float4*)(b + 4) = *(const float4*)&Bs[kk][tn + 4];
#pragma unroll
            for (int i = 0; i < 8; i++)
#pragma unroll
                for (int j = 0; j < 8; j++)
                    acc[i][j] = fmaf(a[i], b[j], acc[i][j]);
        }
        __syncthreads();
    }
#pragma unroll
    for (int i = 0; i < 8; i++) {
        float* cp = g_C + (size_t)(m0 + tm + i) * NC + n0 + tn;
        *(float4*)(cp)     = make_float4(acc[i][0], acc[i][1], acc[i][2], acc[i][3]);
        *(float4*)(cp + 4) = make_float4(acc[i][4], acc[i][5], acc[i][6], acc[i][7]);
    }
}

// ---------------- 3) fused gate + value + x_norm ----------------
__inline__ __device__ float warpSum(float v) {
#pragma unroll
    for (int o = 16; o; o >>= 1) v += __shfl_xor_sync(0xffffffffu, v, o);
    return v;
}

__global__ __launch_bounds__(256)
void gate_kernel(const float* __restrict__ hs,
                 const float* __restrict__ bk, const float* __restrict__ bv,
                 const float* __restrict__ n1w, const float* __restrict__ n2w,
                 const float* __restrict__ scw) {
    int m = blockIdx.x;          // token 0..8191
    int tid = threadIdx.x;
    const float4* hs4 = (const float4*)hs + (size_t)m * (GD / 4);
    const float4* C4  = (const float4*)g_C + (size_t)m * (NC / 4);
    const float4* bk4 = (const float4*)bk;
    const float4* bv4 = (const float4*)bv;
    const float4* w14 = (const float4*)n1w;
    const float4* w24 = (const float4*)n2w;
    const float4* sw4 = (const float4*)scw;

    float sk0 = 0, sk1 = 0, sq0 = 0, sq1 = 0, sp0 = 0, sp1 = 0, sv = 0;
    float4 vr[2];
#pragma unroll
    for (int j = 0; j < 2; j++) {
        int f = tid + 256 * j;                 // float4 idx within D=2048
        float4 v = C4[1024 + f];               // vproj at column 4096
        float4 bb = bv4[f];
        v.x += bb.x; v.y += bb.y; v.z += bb.z; v.w += bb.w;
        vr[j] = v;
        sv += v.x * v.x + v.y * v.y + v.z * v.z + v.w * v.w;
    }
#pragma unroll
    for (int g = 0; g < 2; g++) {
#pragma unroll
        for (int j = 0; j < 2; j++) {
            int f = tid + 256 * j;
            int off = g * 512 + f;
            float4 kp = C4[off];
            float4 kb = bk4[off];
            kp.x += kb.x; kp.y += kb.y; kp.z += kb.z; kp.w += kb.w;
            float4 q = hs4[off];
            float4 w1 = w14[off];
            float4 w2 = w24[off];
            float skk = kp.x * kp.x + kp.y * kp.y + kp.z * kp.z + kp.w * kp.w;
            float sqq = q.x * q.x + q.y * q.y + q.z * q.z + q.w * q.w;
            float spp = kp.x * q.x * w1.x * w2.x + kp.y * q.y * w1.y * w2.y +
                        kp.z * q.z * w1.z * w2.z + kp.w * q.w * w1.w * w2.w;
            if (g == 0) { sk0 += skk; sq0 += sqq; sp0 += spp; }
            else        { sk1 += skk; sq1 += sqq; sp1 += spp; }
        }
    }

    float vals[7] = { sk0, sk1, sq0, sq1, sp0, sp1, sv };
    __shared__ float sh[7][8];
    __shared__ float res[4];     // gate0, gate1, inv0, inv1
    int lane = tid & 31, wid = tid >> 5;
#pragma unroll
    for (int i = 0; i < 7; i++) {
        vals[i] = warpSum(vals[i]);
        if (lane == 0) sh[i][wid] = vals[i];
    }
    __syncthreads();
    if (tid == 0) {
        float t[7];
#pragma unroll
        for (int i = 0; i < 7; i++) {
            float s = 0.f;
#pragma unroll
            for (int w = 0; w < 8; w++) s += sh[i][w];
            t[i] = s;
        }
        const float invD = 1.f / (float)DD;
        const float EPSD = 1.1920929e-07f;   // float32 eps
#pragma unroll
        for (int g = 0; g < 2; g++) {
            float rk = rsqrtf(t[g] * invD + EPSD);
            float rq = rsqrtf(t[2 + g] * invD + EPSD);
            float gp = t[4 + g] * rk * rq * 0.022097086912079612f; // 1/sqrt(2048)
            float a = sqrtf(fmaxf(fabsf(gp), 1e-6f));
            a = (gp > 0.f) ? a : ((gp < 0.f) ? -a : 0.f);
            float gate = 1.f / (1.f + __expf(-a));
            float inv = rsqrtf(gate * gate * (t[6] * invD) + 1e-5f);
            res[g] = gate;
            res[2 + g] = inv;
        }
    }
    __syncthreads();
    float gate0 = res[0], gate1 = res[1], inv0 = res[2], inv1 = res[3];

    float4* V4 = (float4*)g_value + (size_t)m * (GD / 4);
    float4* X4 = (float4*)g_xnorm + (size_t)m * (GD / 4);
#pragma unroll
    for (int g = 0; g < 2; g++) {
        float gate = g ? gate1 : gate0;
        float inv  = g ? inv1 : inv0;
#pragma unroll
        for (int j = 0; j < 2; j++) {
            int f = tid + 256 * j;
            int off = g * 512 + f;
            float4 v = vr[j];
            float4 val = make_float4(gate * v.x, gate * v.y, gate * v.z, gate * v.w);
            float4 sw = sw4[off];
            float4 xn = make_float4(val.x * inv * sw.x, val.y * inv * sw.y,
                                    val.z * inv * sw.z, val.w * inv * sw.w);
            V4[off] = val;
            X4[off] = xn;
        }
    }
}

// ---------------- 4) depthwise dilated causal conv + silu + residual + cache ----------------
__global__ __launch_bounds__(256)
void conv_kernel(const float* __restrict__ cw, float* __restrict__ out,
                 float* __restrict__ cache) {
    int c = blockIdx.x * 256 + threadIdx.x;   // channel 0..4095
    int b = blockIdx.z;
    int l0 = blockIdx.y * 128;
    float w0 = cw[c * 4 + 0], w1 = cw[c * 4 + 1];
    float w2 = cw[c * 4 + 2], w3 = cw[c * 4 + 3];
    const size_t base = ((size_t)b * LL) * GD + c;
#pragma unroll
    for (int r = 0; r < 3; r++) {
        int l = l0 + r;
        float x3 = (l - 3 >= 0) ? g_xnorm[base + (size_t)(l - 3) * GD] : 0.f;
        float x6 = (l - 6 >= 0) ? g_xnorm[base + (size_t)(l - 6) * GD] : 0.f;
        float x9 = (l - 9 >= 0) ? g_xnorm[base + (size_t)(l - 9) * GD] : 0.f;
        for (; l < l0 + 128; l += 3) {
            size_t idx = base + (size_t)l * GD;
            float x0 = g_xnorm[idx];
            float y = fmaf(w3, x0, fmaf(w2, x3, fmaf(w1, x6, w0 * x9)));
            y = y / (1.f + __expf(-y));   // silu
            out[idx] = g_value[idx] + y;
            if (l >= LL - PAD)
                cache[((size_t)b * GD + c) * PAD + (l - (LL - PAD))] = x0;
            x9 = x6; x6 = x3; x3 = x0;
        }
    }
}

// ---------------- launcher ----------------
extern "C" void kernel_launch(void* const* d_in, const int* in_sizes, int n_in,
                              void* d_out, int out_size) {
    const float* hs    = (const float*)d_in[0];
    const int*   ids   = (const int*)d_in[1];
    const float* table = (const float*)d_in[2];
    const float* Wk    = (const float*)d_in[3];
    const float* bk    = (const float*)d_in[4];
    const float* Wv    = (const float*)d_in[5];
    const float* bv    = (const float*)d_in[6];
    const float* n1w   = (const float*)d_in[7];
    const float* n2w   = (const float*)d_in[8];
    const float* cw    = (const float*)d_in[9];
    const float* scw   = (const float*)d_in[10];
    float* out   = (float*)d_out;
    float* cache = out + (size_t)MM * GD;   // output tensor first, then new_cache

    gather_kernel<<<MM, 256>>>(ids, table);
    dim3 ggrid(NC / 128, MM / 128);
    gemm_kernel<<<ggrid, 256>>>(Wk, Wv);
    gate_kernel<<<MM, 256>>>(hs, bk, bv, n1w, n2w, scw);
    dim3 cgrid(GD / 256, LL / 128, BB);
    conv_kernel<<<cgrid, 256>>>(cw, out, cache);
}

// round 4
// speedup vs baseline: 2.2427x; 2.2427x over previous
#include <cuda_runtime.h>
#include <cuda_bf16.h>
#include <math.h>
#include <stdint.h>

// Problem constants
#define BB 4
#define LL 2048
#define GG 2
#define DD 2048
#define HH 16
#define EE 1024          // H*De
#define NN 32768
#define MM (BB*LL)       // 8192 tokens
#define NC 6144          // G*D + D combined GEMM columns
#define GD (GG*DD)       // 4096
#define PAD 9            // (K-1)*DIL

// GEMM tiling
#define KC 64            // K elems per chunk (128 bytes bf16 per row)
#define NCHUNK 48        // 3 passes (hi*hi, lo*hi, hi*lo) x 16 chunks of 64
#define BUF_BYTES 32768  // A tile 16KB + B tile 16KB
#define SMEM_TOTAL (3 * BUF_BYTES)   // 98304

// ---------------- scratch (static device globals; no allocation) ----------------
__device__ __nv_bfloat16 g_Ahi[(size_t)MM * EE];
__device__ __nv_bfloat16 g_Alo[(size_t)MM * EE];
__device__ __nv_bfloat16 g_Bhi[(size_t)NC * EE];
__device__ __nv_bfloat16 g_Blo[(size_t)NC * EE];
__device__ float g_C[(size_t)MM * NC];
__device__ float g_value[(size_t)MM * GD];
__device__ float g_xnorm[(size_t)MM * GD];

// ---------------- PTX helpers (all plain-sm_103-legal: sm_80/75 era) ----------------
__device__ __forceinline__ uint32_t smem_u32(const void* p) {
    uint32_t a;
    asm("{ .reg .u64 t; cvta.to.shared.u64 t, %1; cvt.u32.u64 %0, t; }" : "=r"(a) : "l"(p));
    return a;
}
__device__ __forceinline__ void cp16(uint32_t dst, const void* src) {
    asm volatile("cp.async.cg.shared.global [%0], [%1], 16;\n" :: "r"(dst), "l"(src));
}
__device__ __forceinline__ void ldsm_x4(uint32_t* r, uint32_t addr) {
    asm volatile("ldmatrix.sync.aligned.m8n8.x4.shared.b16 {%0,%1,%2,%3}, [%4];"
                 : "=r"(r[0]), "=r"(r[1]), "=r"(r[2]), "=r"(r[3]) : "r"(addr));
}
__device__ __forceinline__ void mma_bf16(float* d, const uint32_t* a, const uint32_t* b) {
    asm volatile(
        "mma.sync.aligned.m16n8k16.row.col.f32.bf16.bf16.f32 "
        "{%0,%1,%2,%3}, {%4,%5,%6,%7}, {%8,%9}, {%0,%1,%2,%3};"
        : "+f"(d[0]), "+f"(d[1]), "+f"(d[2]), "+f"(d[3])
        : "r"(a[0]), "r"(a[1]), "r"(a[2]), "r"(a[3]), "r"(b[0]), "r"(b[1]));
}

// ---------------- 1) gather embeddings (fp32 -> bf16 hi/lo split) ----------------
__device__ __forceinline__ uint32_t pack2(float a, float b, float* ra, float* rb) {
    __nv_bfloat16 ha = __float2bfloat16(a);
    __nv_bfloat16 hb = __float2bfloat16(b);
    *ra = a - __bfloat162float(ha);
    *rb = b - __bfloat162float(hb);
    return (uint32_t)__bfloat16_as_ushort(ha) | ((uint32_t)__bfloat16_as_ushort(hb) << 16);
}
__device__ __forceinline__ uint32_t pack2lo(float a, float b) {
    return (uint32_t)__bfloat16_as_ushort(__float2bfloat16(a)) |
           ((uint32_t)__bfloat16_as_ushort(__float2bfloat16(b)) << 16);
}

__global__ void gather_kernel(const int* __restrict__ ids,
                              const float* __restrict__ table) {
    int f = blockIdx.x * blockDim.x + threadIdx.x;   // float4 index, total MM*256
    int m  = f >> 8;
    int e4 = f & 255;
    int h  = e4 >> 4;
    int j  = e4 & 15;
    int row = ids[m * HH + h] + h * NN;
    float4 v = ((const float4*)table)[(size_t)row * 16 + j];
    float rx, ry, rz, rw;
    uint2 hi, lo;
    hi.x = pack2(v.x, v.y, &rx, &ry);
    hi.y = pack2(v.z, v.w, &rz, &rw);
    lo.x = pack2lo(rx, ry);
    lo.y = pack2lo(rz, rw);
    ((uint2*)g_Ahi)[(size_t)m * 256 + e4] = hi;
    ((uint2*)g_Alo)[(size_t)m * 256 + e4] = lo;
}

// ---------------- 1b) weight prep: Wk||Wv -> bf16 hi/lo ----------------
__global__ void wprep_kernel(const float* __restrict__ Wk, const float* __restrict__ Wv) {
    int f = blockIdx.x * blockDim.x + threadIdx.x;   // float4 idx, total NC*256
    int n = f >> 8;
    int j = f & 255;
    float4 v = (n < GD) ? ((const float4*)Wk)[(size_t)n * 256 + j]
                        : ((const float4*)Wv)[(size_t)(n - GD) * 256 + j];
    float rx, ry, rz, rw;
    uint2 hi, lo;
    hi.x = pack2(v.x, v.y, &rx, &ry);
    hi.y = pack2(v.z, v.w, &rz, &rw);
    lo.x = pack2lo(rx, ry);
    lo.y = pack2lo(rz, rw);
    ((uint2*)g_Bhi)[(size_t)n * 256 + j] = hi;
    ((uint2*)g_Blo)[(size_t)n * 256 + j] = lo;
}

// ---------------- 2) mma.sync bf16 split GEMM ----------------
// C[m,n] = sum over K''=3072: pass0 Ahi*Bhi, pass1 Alo*Bhi, pass2 Ahi*Blo
// Block 128x128, KC=64, 3-stage cp.async pipeline.
// 8 warps: warp_m = wid&1 (64 rows), warp_n = wid>>1 (32 cols).
__global__ __launch_bounds__(256)
void gemm_mma_kernel() {
    extern __shared__ char smem[];
    uint32_t sbase = smem_u32(smem);
    int tid = threadIdx.x;
    int lane = tid & 31;
    int wid = tid >> 5;
    int m0 = blockIdx.y * 128;
    int n0 = blockIdx.x * 128;
    int m_w = (wid & 1) * 64;
    int n_w = (wid >> 1) * 32;

    // cp.async loader: threads 0-127 load A rows, 128-255 load B rows
    auto issue_loads = [&](int c, int s) {
        int p = c >> 4;
        int kk = (c & 15) * KC;
        int r = tid & 127;
        const __nv_bfloat16* src;
        uint32_t dst;
        if (tid < 128) {
            const __nv_bfloat16* As = (p == 1) ? g_Alo : g_Ahi;
            src = As + (size_t)(m0 + r) * EE + kk;
            dst = sbase + s * BUF_BYTES;
        } else {
            const __nv_bfloat16* Bs = (p == 2) ? g_Blo : g_Bhi;
            src = Bs + (size_t)(n0 + r) * EE + kk;
            dst = sbase + s * BUF_BYTES + 16384;
        }
#pragma unroll
        for (int q = 0; q < 8; q++) {
            uint32_t off = (uint32_t)r * 128 + q * 16;
            uint32_t sw = off ^ ((off >> 3) & 0x70);
            cp16(dst + sw, (const char*)src + q * 16);
        }
        asm volatile("cp.async.commit_group;\n" ::);
    };

    issue_loads(0, 0);
    issue_loads(1, 1);

    float acc[4][4][4];
#pragma unroll
    for (int i = 0; i < 4; i++)
#pragma unroll
        for (int j = 0; j < 4; j++)
#pragma unroll
            for (int k = 0; k < 4; k++) acc[i][j][k] = 0.f;

    // per-lane ldmatrix address components
    uint32_t arow[4], brow[2];
    uint32_t axorv = (uint32_t)((lane & 7) << 4);
    uint32_t ach = (uint32_t)((lane >> 4) * 16);
#pragma unroll
    for (int mt = 0; mt < 4; mt++)
        arow[mt] = (uint32_t)(m_w + mt * 16 + (lane & 15)) * 128;
    uint32_t bch = (uint32_t)(((lane >> 3) & 1) * 16);
#pragma unroll
    for (int nt = 0; nt < 2; nt++)
        brow[nt] = (uint32_t)(n_w + nt * 16 + ((lane >> 4) & 1) * 8 + (lane & 7)) * 128;

    for (int i = 0; i < NCHUNK; i++) {
        int s = i % 3;
        if (i < NCHUNK - 1) asm volatile("cp.async.wait_group 1;\n" ::);
        else                asm volatile("cp.async.wait_group 0;\n" ::);
        __syncthreads();
        if (i + 2 < NCHUNK) issue_loads(i + 2, (i + 2) % 3);

        uint32_t aBase = sbase + s * BUF_BYTES;
        uint32_t bBase = aBase + 16384;
#pragma unroll
        for (int ks = 0; ks < 4; ks++) {
            uint32_t af[4][4], bf[2][4];
#pragma unroll
            for (int mt = 0; mt < 4; mt++)
                ldsm_x4(af[mt], aBase + arow[mt] + (((uint32_t)(ks * 32) + ach) ^ axorv));
#pragma unroll
            for (int nt = 0; nt < 2; nt++)
                ldsm_x4(bf[nt], bBase + brow[nt] + (((uint32_t)(ks * 32) + bch) ^ axorv));
#pragma unroll
            for (int mt = 0; mt < 4; mt++)
#pragma unroll
                for (int j = 0; j < 4; j++)
                    mma_bf16(acc[mt][j], af[mt], &bf[j >> 1][(j & 1) * 2]);
        }
        __syncthreads();
    }

    // epilogue: direct register -> global writes (float2 per pair)
    int grp = lane >> 2;
    int qd  = lane & 3;
#pragma unroll
    for (int mt = 0; mt < 4; mt++) {
        int row = m0 + m_w + mt * 16 + grp;
#pragma unroll
        for (int j = 0; j < 4; j++) {
            int col = n0 + n_w + j * 8 + qd * 2;
            *(float2*)(g_C + (size_t)row * NC + col) =
                make_float2(acc[mt][j][0], acc[mt][j][1]);
            *(float2*)(g_C + (size_t)(row + 8) * NC + col) =
                make_float2(acc[mt][j][2], acc[mt][j][3]);
        }
    }
}

// ---------------- 3) fused gate + value + x_norm ----------------
__inline__ __device__ float warpSum(float v) {
#pragma unroll
    for (int o = 16; o; o >>= 1) v += __shfl_xor_sync(0xffffffffu, v, o);
    return v;
}

__global__ __launch_bounds__(256)
void gate_kernel(const float* __restrict__ hs,
                 const float* __restrict__ bk, const float* __restrict__ bv,
                 const float* __restrict__ n1w, const float* __restrict__ n2w,
                 const float* __restrict__ scw) {
    int m = blockIdx.x;
    int tid = threadIdx.x;
    const float4* hs4 = (const float4*)hs + (size_t)m * (GD / 4);
    const float4* C4  = (const float4*)g_C + (size_t)m * (NC / 4);
    const float4* bk4 = (const float4*)bk;
    const float4* bv4 = (const float4*)bv;
    const float4* w14 = (const float4*)n1w;
    const float4* w24 = (const float4*)n2w;
    const float4* sw4 = (const float4*)scw;

    float sk0 = 0, sk1 = 0, sq0 = 0, sq1 = 0, sp0 = 0, sp1 = 0, sv = 0;
    float4 vr[2];
#pragma unroll
    for (int j = 0; j < 2; j++) {
        int f = tid + 256 * j;
        float4 v = C4[1024 + f];
        float4 bb = bv4[f];
        v.x += bb.x; v.y += bb.y; v.z += bb.z; v.w += bb.w;
        vr[j] = v;
        sv += v.x * v.x + v.y * v.y + v.z * v.z + v.w * v.w;
    }
#pragma unroll
    for (int g = 0; g < 2; g++) {
#pragma unroll
        for (int j = 0; j < 2; j++) {
            int f = tid + 256 * j;
            int off = g * 512 + f;
            float4 kp = C4[off];
            float4 kb = bk4[off];
            kp.x += kb.x; kp.y += kb.y; kp.z += kb.z; kp.w += kb.w;
            float4 q = hs4[off];
            float4 w1 = w14[off];
            float4 w2 = w24[off];
            float skk = kp.x * kp.x + kp.y * kp.y + kp.z * kp.z + kp.w * kp.w;
            float sqq = q.x * q.x + q.y * q.y + q.z * q.z + q.w * q.w;
            float spp = kp.x * q.x * w1.x * w2.x + kp.y * q.y * w1.y * w2.y +
                        kp.z * q.z * w1.z * w2.z + kp.w * q.w * w1.w * w2.w;
            if (g == 0) { sk0 += skk; sq0 += sqq; sp0 += spp; }
            else        { sk1 += skk; sq1 += sqq; sp1 += spp; }
        }
    }

    float vals[7] = { sk0, sk1, sq0, sq1, sp0, sp1, sv };
    __shared__ float sh[7][8];
    __shared__ float res[4];
    int lane = tid & 31, wid = tid >> 5;
#pragma unroll
    for (int i = 0; i < 7; i++) {
        vals[i] = warpSum(vals[i]);
        if (lane == 0) sh[i][wid] = vals[i];
    }
    __syncthreads();
    if (tid == 0) {
        float t[7];
#pragma unroll
        for (int i = 0; i < 7; i++) {
            float s = 0.f;
#pragma unroll
            for (int w = 0; w < 8; w++) s += sh[i][w];
            t[i] = s;
        }
        const float invD = 1.f / (float)DD;
        const float EPSD = 1.1920929e-07f;
#pragma unroll
        for (int g = 0; g < 2; g++) {
            float rk = rsqrtf(t[g] * invD + EPSD);
            float rq = rsqrtf(t[2 + g] * invD + EPSD);
            float gp = t[4 + g] * rk * rq * 0.022097086912079612f;
            float a = sqrtf(fmaxf(fabsf(gp), 1e-6f));
            a = (gp > 0.f) ? a : ((gp < 0.f) ? -a : 0.f);
            float gate = 1.f / (1.f + __expf(-a));
            float inv = rsqrtf(gate * gate * (t[6] * invD) + 1e-5f);
            res[g] = gate;
            res[2 + g] = inv;
        }
    }
    __syncthreads();
    float gate0 = res[0], gate1 = res[1], inv0 = res[2], inv1 = res[3];

    float4* V4 = (float4*)g_value + (size_t)m * (GD / 4);
    float4* X4 = (float4*)g_xnorm + (size_t)m * (GD / 4);
#pragma unroll
    for (int g = 0; g < 2; g++) {
        float gate = g ? gate1 : gate0;
        float inv  = g ? inv1 : inv0;
#pragma unroll
        for (int j = 0; j < 2; j++) {
            int f = tid + 256 * j;
            int off = g * 512 + f;
            float4 v = vr[j];
            float4 val = make_float4(gate * v.x, gate * v.y, gate * v.z, gate * v.w);
            float4 sw = sw4[off];
            float4 xn = make_float4(val.x * inv * sw.x, val.y * inv * sw.y,
                                    val.z * inv * sw.z, val.w * inv * sw.w);
            V4[off] = val;
            X4[off] = xn;
        }
    }
}

// ---------------- 4) conv + silu + residual + cache (2 channels/thread) ----------------
__global__ __launch_bounds__(256)
void conv_kernel(const float* __restrict__ cw, float* __restrict__ out,
                 float* __restrict__ cache) {
    int c2 = blockIdx.x * 256 + threadIdx.x;   // channel pair 0..2047
    int c = c2 * 2;
    int b = blockIdx.z;
    int l0 = blockIdx.y * 128;
    float4 wA = *(const float4*)(cw + c * 4);
    float4 wB = *(const float4*)(cw + c * 4 + 4);
    const size_t base = ((size_t)b * LL) * GD + c;
#pragma unroll
    for (int r = 0; r < 3; r++) {
        int l = l0 + r;
        float2 zz = make_float2(0.f, 0.f);
        float2 x3 = (l - 3 >= 0) ? *(const float2*)(g_xnorm + base + (size_t)(l - 3) * GD) : zz;
        float2 x6 = (l - 6 >= 0) ? *(const float2*)(g_xnorm + base + (size_t)(l - 6) * GD) : zz;
        float2 x9 = (l - 9 >= 0) ? *(const float2*)(g_xnorm + base + (size_t)(l - 9) * GD) : zz;
        for (; l < l0 + 128; l += 3) {
            size_t idx = base + (size_t)l * GD;
            float2 x0 = *(const float2*)(g_xnorm + idx);
            float ya = fmaf(wA.w, x0.x, fmaf(wA.z, x3.x, fmaf(wA.y, x6.x, wA.x * x9.x)));
            float yb = fmaf(wB.w, x0.y, fmaf(wB.z, x3.y, fmaf(wB.y, x6.y, wB.x * x9.y)));
            ya = ya / (1.f + __expf(-ya));
            yb = yb / (1.f + __expf(-yb));
            float2 v = *(const float2*)(g_value + idx);
            float2 o = make_float2(v.x + ya, v.y + yb);
            *(float2*)(out + idx) = o;
            if (l >= LL - PAD) {
                cache[((size_t)b * GD + c) * PAD + (l - (LL - PAD))] = x0.x;
                cache[((size_t)b * GD + c + 1) * PAD + (l - (LL - PAD))] = x0.y;
            }
            x9 = x6; x6 = x3; x3 = x0;
        }
    }
}

// ---------------- launcher ----------------
extern "C" void kernel_launch(void* const* d_in, const int* in_sizes, int n_in,
                              void* d_out, int out_size) {
    const float* hs    = (const float*)d_in[0];
    const int*   ids   = (const int*)d_in[1];
    const float* table = (const float*)d_in[2];
    const float* Wk    = (const float*)d_in[3];
    const float* bk    = (const float*)d_in[4];
    const float* Wv    = (const float*)d_in[5];
    const float* bv    = (const float*)d_in[6];
    const float* n1w   = (const float*)d_in[7];
    const float* n2w   = (const float*)d_in[8];
    const float* cw    = (const float*)d_in[9];
    const float* scw   = (const float*)d_in[10];
    float* out   = (float*)d_out;
    float* cache = out + (size_t)MM * GD;

    cudaFuncSetAttribute(gemm_mma_kernel,
                         cudaFuncAttributeMaxDynamicSharedMemorySize, SMEM_TOTAL);

    gather_kernel<<<MM, 256>>>(ids, table);
    wprep_kernel<<<NC, 256>>>(Wk, Wv);
    dim3 ggrid(NC / 128, MM / 128);
    gemm_mma_kernel<<<ggrid, 256, SMEM_TOTAL>>>();
    gate_kernel<<<MM, 256>>>(hs, bk, bv, n1w, n2w, scw);
    dim3 cgrid(GD / 512, LL / 128, BB);
    conv_kernel<<<cgrid, 256>>>(cw, out, cache);
}

// round 5
// speedup vs baseline: 2.5152x; 1.1215x over previous
#include <cuda_runtime.h>
#include <cuda_bf16.h>
#include <math.h>
#include <stdint.h>

// Problem constants
#define BB 4
#define LL 2048
#define GG 2
#define DD 2048
#define HH 16
#define EE 1024          // H*De
#define NN 32768
#define MM (BB*LL)       // 8192 tokens
#define NC 6144          // G*D + D combined GEMM columns
#define GD (GG*DD)       // 4096
#define PAD 9            // (K-1)*DIL

// GEMM tiling
#define KC 64            // K elems per chunk (128 bytes bf16 per row)
#define NCHUNK 48        // 3 passes (hi*hi, lo*hi, hi*lo) x 16 chunks of 64
#define BUF_BYTES 32768  // A tile 16KB + B tile 16KB
#define SMEM_TOTAL (3 * BUF_BYTES)   // 98304

// ---------------- scratch (static device globals; no allocation) ----------------
__device__ __nv_bfloat16 g_Ahi[(size_t)MM * EE];
__device__ __nv_bfloat16 g_Alo[(size_t)MM * EE];
__device__ __nv_bfloat16 g_Bhi[(size_t)NC * EE];
__device__ __nv_bfloat16 g_Blo[(size_t)NC * EE];
__device__ float g_C[(size_t)MM * NC];
__device__ float g_value[(size_t)MM * GD];
__device__ float g_xnorm[(size_t)MM * GD];

// ---------------- PTX helpers (plain-sm_103-legal) ----------------
__device__ __forceinline__ uint32_t smem_u32(const void* p) {
    uint32_t a;
    asm("{ .reg .u64 t; cvta.to.shared.u64 t, %1; cvt.u32.u64 %0, t; }" : "=r"(a) : "l"(p));
    return a;
}
__device__ __forceinline__ void cp16(uint32_t dst, const void* src) {
    asm volatile("cp.async.cg.shared.global [%0], [%1], 16;\n" :: "r"(dst), "l"(src));
}
__device__ __forceinline__ void ldsm_x4(uint32_t* r, uint32_t addr) {
    asm volatile("ldmatrix.sync.aligned.m8n8.x4.shared.b16 {%0,%1,%2,%3}, [%4];"
                 : "=r"(r[0]), "=r"(r[1]), "=r"(r[2]), "=r"(r[3]) : "r"(addr));
}
__device__ __forceinline__ void mma_bf16(float* d, const uint32_t* a, const uint32_t* b) {
    asm volatile(
        "mma.sync.aligned.m16n8k16.row.col.f32.bf16.bf16.f32 "
        "{%0,%1,%2,%3}, {%4,%5,%6,%7}, {%8,%9}, {%0,%1,%2,%3};"
        : "+f"(d[0]), "+f"(d[1]), "+f"(d[2]), "+f"(d[3])
        : "r"(a[0]), "r"(a[1]), "r"(a[2]), "r"(a[3]), "r"(b[0]), "r"(b[1]));
}

// ---------------- 1) gather embeddings (fp32 -> bf16 hi/lo split) ----------------
__device__ __forceinline__ uint32_t pack2(float a, float b, float* ra, float* rb) {
    __nv_bfloat16 ha = __float2bfloat16(a);
    __nv_bfloat16 hb = __float2bfloat16(b);
    *ra = a - __bfloat162float(ha);
    *rb = b - __bfloat162float(hb);
    return (uint32_t)__bfloat16_as_ushort(ha) | ((uint32_t)__bfloat16_as_ushort(hb) << 16);
}
__device__ __forceinline__ uint32_t pack2lo(float a, float b) {
    return (uint32_t)__bfloat16_as_ushort(__float2bfloat16(a)) |
           ((uint32_t)__bfloat16_as_ushort(__float2bfloat16(b)) << 16);
}

__global__ void gather_kernel(const int* __restrict__ ids,
                              const float* __restrict__ table) {
    int f = blockIdx.x * blockDim.x + threadIdx.x;   // float4 index, total MM*256
    int m  = f >> 8;
    int e4 = f & 255;
    int h  = e4 >> 4;
    int j  = e4 & 15;
    int row = ids[m * HH + h] + h * NN;
    float4 v = ((const float4*)table)[(size_t)row * 16 + j];
    float rx, ry, rz, rw;
    uint2 hi, lo;
    hi.x = pack2(v.x, v.y, &rx, &ry);
    hi.y = pack2(v.z, v.w, &rz, &rw);
    lo.x = pack2lo(rx, ry);
    lo.y = pack2lo(rz, rw);
    ((uint2*)g_Ahi)[(size_t)m * 256 + e4] = hi;
    ((uint2*)g_Alo)[(size_t)m * 256 + e4] = lo;
}

// ---------------- 1b) weight prep: Wk||Wv -> bf16 hi/lo ----------------
__global__ void wprep_kernel(const float* __restrict__ Wk, const float* __restrict__ Wv) {
    int f = blockIdx.x * blockDim.x + threadIdx.x;   // float4 idx, total NC*256
    int n = f >> 8;
    int j = f & 255;
    float4 v = (n < GD) ? ((const float4*)Wk)[(size_t)n * 256 + j]
                        : ((const float4*)Wv)[(size_t)(n - GD) * 256 + j];
    float rx, ry, rz, rw;
    uint2 hi, lo;
    hi.x = pack2(v.x, v.y, &rx, &ry);
    hi.y = pack2(v.z, v.w, &rz, &rw);
    lo.x = pack2lo(rx, ry);
    lo.y = pack2lo(rz, rw);
    ((uint2*)g_Bhi)[(size_t)n * 256 + j] = hi;
    ((uint2*)g_Blo)[(size_t)n * 256 + j] = lo;
}

// ---------------- 2) mma.sync bf16 split GEMM ----------------
// Block 128x128, KC=64, 3-stage cp.async pipeline, single sync per chunk.
// 4 warps, each owning a 64x64 sub-tile.
__global__ __launch_bounds__(128, 2)
void gemm_mma_kernel() {
    extern __shared__ char smem[];
    uint32_t sbase = smem_u32(smem);
    int tid = threadIdx.x;
    int lane = tid & 31;
    int wid = tid >> 5;
    int m0 = blockIdx.y * 128;
    int n0 = blockIdx.x * 128;
    int m_w = (wid & 1) * 64;
    int n_w = (wid >> 1) * 64;

    // cp.async loader: each of 128 threads loads one A row + one B row (128B each)
    auto issue_loads = [&](int c, int s) {
        int p = c >> 4;
        int kk = (c & 15) * KC;
        const __nv_bfloat16* As = (p == 1) ? g_Alo : g_Ahi;
        const __nv_bfloat16* Bs = (p == 2) ? g_Blo : g_Bhi;
        const char* asrc = (const char*)(As + (size_t)(m0 + tid) * EE + kk);
        const char* bsrc = (const char*)(Bs + (size_t)(n0 + tid) * EE + kk);
        uint32_t adst = sbase + s * BUF_BYTES;
        uint32_t bdst = adst + 16384;
#pragma unroll
        for (int q = 0; q < 8; q++) {
            uint32_t off = (uint32_t)tid * 128 + q * 16;
            uint32_t sw = off ^ ((off >> 3) & 0x70);
            cp16(adst + sw, asrc + q * 16);
            cp16(bdst + sw, bsrc + q * 16);
        }
        asm volatile("cp.async.commit_group;\n" ::);
    };

    issue_loads(0, 0);
    issue_loads(1, 1);

    float acc[4][8][4];
#pragma unroll
    for (int i = 0; i < 4; i++)
#pragma unroll
        for (int j = 0; j < 8; j++)
#pragma unroll
            for (int k = 0; k < 4; k++) acc[i][j][k] = 0.f;

    // per-lane ldmatrix address components (same mapping validated in R4)
    uint32_t arow[4], brow[4];
    uint32_t axorv = (uint32_t)((lane & 7) << 4);
    uint32_t ach = (uint32_t)((lane >> 4) * 16);
#pragma unroll
    for (int mt = 0; mt < 4; mt++)
        arow[mt] = (uint32_t)(m_w + mt * 16 + (lane & 15)) * 128;
    uint32_t bch = (uint32_t)(((lane >> 3) & 1) * 16);
#pragma unroll
    for (int nt = 0; nt < 4; nt++)
        brow[nt] = (uint32_t)(n_w + nt * 16 + ((lane >> 4) & 1) * 8 + (lane & 7)) * 128;

    for (int i = 0; i < NCHUNK; i++) {
        int s = i % 3;
        if (i < NCHUNK - 1) asm volatile("cp.async.wait_group 1;\n" ::);
        else                asm volatile("cp.async.wait_group 0;\n" ::);
        __syncthreads();
        if (i + 2 < NCHUNK) issue_loads(i + 2, (i + 2) % 3);

        uint32_t aBase = sbase + s * BUF_BYTES;
        uint32_t bBase = aBase + 16384;
#pragma unroll
        for (int ks = 0; ks < 4; ks++) {
            uint32_t af[4][4], bf[4][4];
#pragma unroll
            for (int mt = 0; mt < 4; mt++)
                ldsm_x4(af[mt], aBase + arow[mt] + (((uint32_t)(ks * 32) + ach) ^ axorv));
#pragma unroll
            for (int nt = 0; nt < 4; nt++)
                ldsm_x4(bf[nt], bBase + brow[nt] + (((uint32_t)(ks * 32) + bch) ^ axorv));
#pragma unroll
            for (int mt = 0; mt < 4; mt++)
#pragma unroll
                for (int j = 0; j < 8; j++)
                    mma_bf16(acc[mt][j], af[mt], &bf[j >> 1][(j & 1) * 2]);
        }
        // no trailing sync: next iteration's top sync protects buffer reuse
    }

    // epilogue: direct register -> global writes (float2 pairs)
    int grp = lane >> 2;
    int qd  = lane & 3;
#pragma unroll
    for (int mt = 0; mt < 4; mt++) {
        int row = m0 + m_w + mt * 16 + grp;
#pragma unroll
        for (int j = 0; j < 8; j++) {
            int col = n0 + n_w + j * 8 + qd * 2;
            *(float2*)(g_C + (size_t)row * NC + col) =
                make_float2(acc[mt][j][0], acc[mt][j][1]);
            *(float2*)(g_C + (size_t)(row + 8) * NC + col) =
                make_float2(acc[mt][j][2], acc[mt][j][3]);
        }
    }
}

// ---------------- 3) fused gate + value + x_norm ----------------
__inline__ __device__ float warpSum(float v) {
#pragma unroll
    for (int o = 16; o; o >>= 1) v += __shfl_xor_sync(0xffffffffu, v, o);
    return v;
}

__global__ __launch_bounds__(256)
void gate_kernel(const float* __restrict__ hs,
                 const float* __restrict__ bk, const float* __restrict__ bv,
                 const float* __restrict__ n1w, const float* __restrict__ n2w,
                 const float* __restrict__ scw) {
    int m = blockIdx.x;
    int tid = threadIdx.x;
    const float4* hs4 = (const float4*)hs + (size_t)m * (GD / 4);
    const float4* C4  = (const float4*)g_C + (size_t)m * (NC / 4);
    const float4* bk4 = (const float4*)bk;
    const float4* bv4 = (const float4*)bv;
    const float4* w14 = (const float4*)n1w;
    const float4* w24 = (const float4*)n2w;
    const float4* sw4 = (const float4*)scw;

    float sk0 = 0, sk1 = 0, sq0 = 0, sq1 = 0, sp0 = 0, sp1 = 0, sv = 0;
    float4 vr[2];
#pragma unroll
    for (int j = 0; j < 2; j++) {
        int f = tid + 256 * j;
        float4 v = C4[1024 + f];
        float4 bb = bv4[f];
        v.x += bb.x; v.y += bb.y; v.z += bb.z; v.w += bb.w;
        vr[j] = v;
        sv += v.x * v.x + v.y * v.y + v.z * v.z + v.w * v.w;
    }
#pragma unroll
    for (int g = 0; g < 2; g++) {
#pragma unroll
        for (int j = 0; j < 2; j++) {
            int f = tid + 256 * j;
            int off = g * 512 + f;
            float4 kp = C4[off];
            float4 kb = bk4[off];
            kp.x += kb.x; kp.y += kb.y; kp.z += kb.z; kp.w += kb.w;
            float4 q = hs4[off];
            float4 w1 = w14[off];
            float4 w2 = w24[off];
            float skk = kp.x * kp.x + kp.y * kp.y + kp.z * kp.z + kp.w * kp.w;
            float sqq = q.x * q.x + q.y * q.y + q.z * q.z + q.w * q.w;
            float spp = kp.x * q.x * w1.x * w2.x + kp.y * q.y * w1.y * w2.y +
                        kp.z * q.z * w1.z * w2.z + kp.w * q.w * w1.w * w2.w;
            if (g == 0) { sk0 += skk; sq0 += sqq; sp0 += spp; }
            else        { sk1 += skk; sq1 += sqq; sp1 += spp; }
        }
    }

    float vals[7] = { sk0, sk1, sq0, sq1, sp0, sp1, sv };
    __shared__ float sh[7][8];
    __shared__ float res[4];
    int lane = tid & 31, wid = tid >> 5;
#pragma unroll
    for (int i = 0; i < 7; i++) {
        vals[i] = warpSum(vals[i]);
        if (lane == 0) sh[i][wid] = vals[i];
    }
    __syncthreads();
    if (tid == 0) {
        float t[7];
#pragma unroll
        for (int i = 0; i < 7; i++) {
            float s = 0.f;
#pragma unroll
            for (int w = 0; w < 8; w++) s += sh[i][w];
            t[i] = s;
        }
        const float invD = 1.f / (float)DD;
        const float EPSD = 1.1920929e-07f;
#pragma unroll
        for (int g = 0; g < 2; g++) {
            float rk = rsqrtf(t[g] * invD + EPSD);
            float rq = rsqrtf(t[2 + g] * invD + EPSD);
            float gp = t[4 + g] * rk * rq * 0.022097086912079612f;
            float a = sqrtf(fmaxf(fabsf(gp), 1e-6f));
            a = (gp > 0.f) ? a : ((gp < 0.f) ? -a : 0.f);
            float gate = 1.f / (1.f + __expf(-a));
            float inv = rsqrtf(gate * gate * (t[6] * invD) + 1e-5f);
            res[g] = gate;
            res[2 + g] = inv;
        }
    }
    __syncthreads();
    float gate0 = res[0], gate1 = res[1], inv0 = res[2], inv1 = res[3];

    float4* V4 = (float4*)g_value + (size_t)m * (GD / 4);
    float4* X4 = (float4*)g_xnorm + (size_t)m * (GD / 4);
#pragma unroll
    for (int g = 0; g < 2; g++) {
        float gate = g ? gate1 : gate0;
        float inv  = g ? inv1 : inv0;
#pragma unroll
        for (int j = 0; j < 2; j++) {
            int f = tid + 256 * j;
            int off = g * 512 + f;
            float4 v = vr[j];
            float4 val = make_float4(gate * v.x, gate * v.y, gate * v.z, gate * v.w);
            float4 sw = sw4[off];
            float4 xn = make_float4(val.x * inv * sw.x, val.y * inv * sw.y,
                                    val.z * inv * sw.z, val.w * inv * sw.w);
            V4[off] = val;
            X4[off] = xn;
        }
    }
}

// ---------------- 4) conv + silu + residual + cache (2 channels/thread, 64-l blocks) ----------------
__global__ __launch_bounds__(256)
void conv_kernel(const float* __restrict__ cw, float* __restrict__ out,
                 float* __restrict__ cache) {
    int c2 = blockIdx.x * 256 + threadIdx.x;   // channel pair 0..2047
    int c = c2 * 2;
    int b = blockIdx.z;
    int l0 = blockIdx.y * 64;
    float4 wA = *(const float4*)(cw + c * 4);
    float4 wB = *(const float4*)(cw + c * 4 + 4);
    const size_t base = ((size_t)b * LL) * GD + c;
#pragma unroll
    for (int r = 0; r < 3; r++) {
        int l = l0 + r;
        float2 zz = make_float2(0.f, 0.f);
        float2 x3 = (l - 3 >= 0) ? *(const float2*)(g_xnorm + base + (size_t)(l - 3) * GD) : zz;
        float2 x6 = (l - 6 >= 0) ? *(const float2*)(g_xnorm + base + (size_t)(l - 6) * GD) : zz;
        float2 x9 = (l - 9 >= 0) ? *(const float2*)(g_xnorm + base + (size_t)(l - 9) * GD) : zz;
        for (; l < l0 + 64; l += 3) {
            size_t idx = base + (size_t)l * GD;
            float2 x0 = *(const float2*)(g_xnorm + idx);
            float ya = fmaf(wA.w, x0.x, fmaf(wA.z, x3.x, fmaf(wA.y, x6.x, wA.x * x9.x)));
            float yb = fmaf(wB.w, x0.y, fmaf(wB.z, x3.y, fmaf(wB.y, x6.y, wB.x * x9.y)));
            ya = ya / (1.f + __expf(-ya));
            yb = yb / (1.f + __expf(-yb));
            float2 v = *(const float2*)(g_value + idx);
            float2 o = make_float2(v.x + ya, v.y + yb);
            *(float2*)(out + idx) = o;
            if (l >= LL - PAD) {
                cache[((size_t)b * GD + c) * PAD + (l - (LL - PAD))] = x0.x;
                cache[((size_t)b * GD + c + 1) * PAD + (l - (LL - PAD))] = x0.y;
            }
            x9 = x6; x6 = x3; x3 = x0;
        }
    }
}

// ---------------- launcher ----------------
extern "C" void kernel_launch(void* const* d_in, const int* in_sizes, int n_in,
                              void* d_out, int out_size) {
    const float* hs    = (const float*)d_in[0];
    const int*   ids   = (const int*)d_in[1];
    const float* table = (const float*)d_in[2];
    const float* Wk    = (const float*)d_in[3];
    const float* bk    = (const float*)d_in[4];
    const float* Wv    = (const float*)d_in[5];
    const float* bv    = (const float*)d_in[6];
    const float* n1w   = (const float*)d_in[7];
    const float* n2w   = (const float*)d_in[8];
    const float* cw    = (const float*)d_in[9];
    const float* scw   = (const float*)d_in[10];
    float* out   = (float*)d_out;
    float* cache = out + (size_t)MM * GD;

    cudaFuncSetAttribute(gemm_mma_kernel,
                         cudaFuncAttributeMaxDynamicSharedMemorySize, SMEM_TOTAL);

    gather_kernel<<<MM, 256>>>(ids, table);
    wprep_kernel<<<NC, 256>>>(Wk, Wv);
    dim3 ggrid(NC / 128, MM / 128);
    gemm_mma_kernel<<<ggrid, 128, SMEM_TOTAL>>>();
    gate_kernel<<<MM, 256>>>(hs, bk, bv, n1w, n2w, scw);
    dim3 cgrid(GD / 512, LL / 64, BB);
    conv_kernel<<<cgrid, 256>>>(cw, out, cache);
}

// round 6
// speedup vs baseline: 3.4553x; 1.3738x over previous
#include <cuda_runtime.h>
#include <cuda_fp16.h>
#include <math.h>
#include <stdint.h>

// Problem constants
#define BB 4
#define LL 2048
#define GG 2
#define DD 2048
#define HH 16
#define EE 1024          // H*De
#define NN 32768
#define MM (BB*LL)       // 8192 tokens
#define NC 6144          // G*D + D combined GEMM columns
#define GD (GG*DD)       // 4096
#define PAD 9            // (K-1)*DIL

// GEMM tiling
#define KC 64            // K elems per chunk (128 bytes fp16 per row)
#define NCHUNK 32        // 2 passes (Ahi*Bhi, Alo*Bhi) x 16 chunks of 64
#define BUF_BYTES 32768  // A tile 16KB + B tile 16KB
#define SMEM_TOTAL (3 * BUF_BYTES)   // 98304

// ---------------- scratch (static device globals; no allocation) ----------------
__device__ __half g_Ahi[(size_t)MM * EE];
__device__ __half g_Alo[(size_t)MM * EE];
__device__ __half g_Bhi[(size_t)NC * EE];
__device__ float g_C[(size_t)MM * NC];
__device__ float g_value[(size_t)MM * GD];
__device__ float g_xnorm[(size_t)MM * GD];

// ---------------- PTX helpers (plain-sm_103-legal) ----------------
__device__ __forceinline__ uint32_t smem_u32(const void* p) {
    uint32_t a;
    asm("{ .reg .u64 t; cvta.to.shared.u64 t, %1; cvt.u32.u64 %0, t; }" : "=r"(a) : "l"(p));
    return a;
}
__device__ __forceinline__ void cp16(uint32_t dst, const void* src) {
    asm volatile("cp.async.cg.shared.global [%0], [%1], 16;\n" :: "r"(dst), "l"(src));
}
__device__ __forceinline__ void ldsm_x4(uint32_t* r, uint32_t addr) {
    asm volatile("ldmatrix.sync.aligned.m8n8.x4.shared.b16 {%0,%1,%2,%3}, [%4];"
                 : "=r"(r[0]), "=r"(r[1]), "=r"(r[2]), "=r"(r[3]) : "r"(addr));
}
__device__ __forceinline__ void mma_fp16(float* d, const uint32_t* a, const uint32_t* b) {
    asm volatile(
        "mma.sync.aligned.m16n8k16.row.col.f32.f16.f16.f32 "
        "{%0,%1,%2,%3}, {%4,%5,%6,%7}, {%8,%9}, {%0,%1,%2,%3};"
        : "+f"(d[0]), "+f"(d[1]), "+f"(d[2]), "+f"(d[3])
        : "r"(a[0]), "r"(a[1]), "r"(a[2]), "r"(a[3]), "r"(b[0]), "r"(b[1]));
}

// ---------------- 1) gather embeddings (fp32 -> fp16 hi/lo split) ----------------
__device__ __forceinline__ uint32_t pack2h(float a, float b, float* ra, float* rb) {
    __half ha = __float2half_rn(a);
    __half hb = __float2half_rn(b);
    *ra = a - __half2float(ha);
    *rb = b - __half2float(hb);
    return (uint32_t)__half_as_ushort(ha) | ((uint32_t)__half_as_ushort(hb) << 16);
}
__device__ __forceinline__ uint32_t pack2hlo(float a, float b) {
    return (uint32_t)__half_as_ushort(__float2half_rn(a)) |
           ((uint32_t)__half_as_ushort(__float2half_rn(b)) << 16);
}

__global__ void gather_kernel(const int* __restrict__ ids,
                              const float* __restrict__ table) {
    int f = blockIdx.x * blockDim.x + threadIdx.x;   // float4 index, total MM*256
    int m  = f >> 8;
    int e4 = f & 255;
    int h  = e4 >> 4;
    int j  = e4 & 15;
    int row = ids[m * HH + h] + h * NN;
    float4 v = ((const float4*)table)[(size_t)row * 16 + j];
    float rx, ry, rz, rw;
    uint2 hi, lo;
    hi.x = pack2h(v.x, v.y, &rx, &ry);
    hi.y = pack2h(v.z, v.w, &rz, &rw);
    lo.x = pack2hlo(rx, ry);
    lo.y = pack2hlo(rz, rw);
    ((uint2*)g_Ahi)[(size_t)m * 256 + e4] = hi;
    ((uint2*)g_Alo)[(size_t)m * 256 + e4] = lo;
}

// ---------------- 1b) weight prep: Wk||Wv -> fp16 hi only ----------------
__global__ void wprep_kernel(const float* __restrict__ Wk, const float* __restrict__ Wv) {
    int f = blockIdx.x * blockDim.x + threadIdx.x;   // float4 idx, total NC*256
    int n = f >> 8;
    int j = f & 255;
    float4 v = (n < GD) ? ((const float4*)Wk)[(size_t)n * 256 + j]
                        : ((const float4*)Wv)[(size_t)(n - GD) * 256 + j];
    uint2 hi;
    hi.x = pack2hlo(v.x, v.y);
    hi.y = pack2hlo(v.z, v.w);
    ((uint2*)g_Bhi)[(size_t)n * 256 + j] = hi;
}

// ---------------- 2) mma.sync fp16 split GEMM ----------------
// C = Ahi*Bhi + Alo*Bhi (fp32 accumulate). Block 128x128, KC=64,
// 3-stage cp.async pipeline, fragment double-buffering, 4 warps (64x64 each).
__global__ __launch_bounds__(128, 2)
void gemm_mma_kernel() {
    extern __shared__ char smem[];
    uint32_t sbase = smem_u32(smem);
    int tid = threadIdx.x;
    int lane = tid & 31;
    int wid = tid >> 5;
    int m0 = blockIdx.y * 128;
    int n0 = blockIdx.x * 128;
    int m_w = (wid & 1) * 64;
    int n_w = (wid >> 1) * 64;

    // cp.async loader: each of 128 threads loads one A row + one B row (128B each)
    auto issue_loads = [&](int c, int s) {
        int p = c >> 4;                 // 0 -> Ahi, 1 -> Alo
        int kk = (c & 15) * KC;
        const __half* As = p ? g_Alo : g_Ahi;
        const char* asrc = (const char*)(As + (size_t)(m0 + tid) * EE + kk);
        const char* bsrc = (const char*)(g_Bhi + (size_t)(n0 + tid) * EE + kk);
        uint32_t adst = sbase + s * BUF_BYTES;
        uint32_t bdst = adst + 16384;
#pragma unroll
        for (int q = 0; q < 8; q++) {
            uint32_t off = (uint32_t)tid * 128 + q * 16;
            uint32_t sw = off ^ ((off >> 3) & 0x70);
            cp16(adst + sw, asrc + q * 16);
            cp16(bdst + sw, bsrc + q * 16);
        }
        asm volatile("cp.async.commit_group;\n" ::);
    };

    issue_loads(0, 0);
    issue_loads(1, 1);

    float acc[4][8][4];
#pragma unroll
    for (int i = 0; i < 4; i++)
#pragma unroll
        for (int j = 0; j < 8; j++)
#pragma unroll
            for (int k = 0; k < 4; k++) acc[i][j][k] = 0.f;

    // per-lane ldmatrix address components (mapping validated in R4/R5)
    uint32_t arow[4], brow[4];
    uint32_t axorv = (uint32_t)((lane & 7) << 4);
    uint32_t ach = (uint32_t)((lane >> 4) * 16);
#pragma unroll
    for (int mt = 0; mt < 4; mt++)
        arow[mt] = (uint32_t)(m_w + mt * 16 + (lane & 15)) * 128;
    uint32_t bch = (uint32_t)(((lane >> 3) & 1) * 16);
#pragma unroll
    for (int nt = 0; nt < 4; nt++)
        brow[nt] = (uint32_t)(n_w + nt * 16 + ((lane >> 4) & 1) * 8 + (lane & 7)) * 128;

    uint32_t af[2][4][4], bf[2][4][4];

    for (int i = 0; i < NCHUNK; i++) {
        int s = i % 3;
        if (i < NCHUNK - 1) asm volatile("cp.async.wait_group 1;\n" ::);
        else                asm volatile("cp.async.wait_group 0;\n" ::);
        __syncthreads();
        if (i + 2 < NCHUNK) issue_loads(i + 2, (i + 2) % 3);

        uint32_t aBase = sbase + s * BUF_BYTES;
        uint32_t bBase = aBase + 16384;

        // preload ks=0 fragments
#pragma unroll
        for (int mt = 0; mt < 4; mt++)
            ldsm_x4(af[0][mt], aBase + arow[mt] + (ach ^ axorv));
#pragma unroll
        for (int nt = 0; nt < 4; nt++)
            ldsm_x4(bf[0][nt], bBase + brow[nt] + (bch ^ axorv));

#pragma unroll
        for (int ks = 0; ks < 4; ks++) {
            int cur = ks & 1, nxt = cur ^ 1;
            if (ks < 3) {
                uint32_t ko = (uint32_t)((ks + 1) * 32);
#pragma unroll
                for (int mt = 0; mt < 4; mt++)
                    ldsm_x4(af[nxt][mt], aBase + arow[mt] + ((ko + ach) ^ axorv));
#pragma unroll
                for (int nt = 0; nt < 4; nt++)
                    ldsm_x4(bf[nxt][nt], bBase + brow[nt] + ((ko + bch) ^ axorv));
            }
#pragma unroll
            for (int mt = 0; mt < 4; mt++)
#pragma unroll
                for (int j = 0; j < 8; j++)
                    mma_fp16(acc[mt][j], af[cur][mt], &bf[cur][j >> 1][(j & 1) * 2]);
        }
        // no trailing sync: next iteration's top sync protects buffer reuse
    }

    // epilogue: direct register -> global writes (float2 pairs)
    int grp = lane >> 2;
    int qd  = lane & 3;
#pragma unroll
    for (int mt = 0; mt < 4; mt++) {
        int row = m0 + m_w + mt * 16 + grp;
#pragma unroll
        for (int j = 0; j < 8; j++) {
            int col = n0 + n_w + j * 8 + qd * 2;
            *(float2*)(g_C + (size_t)row * NC + col) =
                make_float2(acc[mt][j][0], acc[mt][j][1]);
            *(float2*)(g_C + (size_t)(row + 8) * NC + col) =
                make_float2(acc[mt][j][2], acc[mt][j][3]);
        }
    }
}

// ---------------- 3) fused gate + value + x_norm ----------------
__inline__ __device__ float warpSum(float v) {
#pragma unroll
    for (int o = 16; o; o >>= 1) v += __shfl_xor_sync(0xffffffffu, v, o);
    return v;
}

__global__ __launch_bounds__(256)
void gate_kernel(const float* __restrict__ hs,
                 const float* __restrict__ bk, const float* __restrict__ bv,
                 const float* __restrict__ n1w, const float* __restrict__ n2w,
                 const float* __restrict__ scw) {
    int m = blockIdx.x;
    int tid = threadIdx.x;
    const float4* hs4 = (const float4*)hs + (size_t)m * (GD / 4);
    const float4* C4  = (const float4*)g_C + (size_t)m * (NC / 4);
    const float4* bk4 = (const float4*)bk;
    const float4* bv4 = (const float4*)bv;
    const float4* w14 = (const float4*)n1w;
    const float4* w24 = (const float4*)n2w;
    const float4* sw4 = (const float4*)scw;

    float sk0 = 0, sk1 = 0, sq0 = 0, sq1 = 0, sp0 = 0, sp1 = 0, sv = 0;
    float4 vr[2];
#pragma unroll
    for (int j = 0; j < 2; j++) {
        int f = tid + 256 * j;
        float4 v = C4[1024 + f];
        float4 bb = bv4[f];
        v.x += bb.x; v.y += bb.y; v.z += bb.z; v.w += bb.w;
        vr[j] = v;
        sv += v.x * v.x + v.y * v.y + v.z * v.z + v.w * v.w;
    }
#pragma unroll
    for (int g = 0; g < 2; g++) {
#pragma unroll
        for (int j = 0; j < 2; j++) {
            int f = tid + 256 * j;
            int off = g * 512 + f;
            float4 kp = C4[off];
            float4 kb = bk4[off];
            kp.x += kb.x; kp.y += kb.y; kp.z += kb.z; kp.w += kb.w;
            float4 q = hs4[off];
            float4 w1 = w14[off];
            float4 w2 = w24[off];
            float skk = kp.x * kp.x + kp.y * kp.y + kp.z * kp.z + kp.w * kp.w;
            float sqq = q.x * q.x + q.y * q.y + q.z * q.z + q.w * q.w;
            float spp = kp.x * q.x * w1.x * w2.x + kp.y * q.y * w1.y * w2.y +
                        kp.z * q.z * w1.z * w2.z + kp.w * q.w * w1.w * w2.w;
            if (g == 0) { sk0 += skk; sq0 += sqq; sp0 += spp; }
            else        { sk1 += skk; sq1 += sqq; sp1 += spp; }
        }
    }

    float vals[7] = { sk0, sk1, sq0, sq1, sp0, sp1, sv };
    __shared__ float sh[7][8];
    __shared__ float res[4];
    int lane = tid & 31, wid = tid >> 5;
#pragma unroll
    for (int i = 0; i < 7; i++) {
        vals[i] = warpSum(vals[i]);
        if (lane == 0) sh[i][wid] = vals[i];
    }
    __syncthreads();
    if (tid == 0) {
        float t[7];
#pragma unroll
        for (int i = 0; i < 7; i++) {
            float s = 0.f;
#pragma unroll
            for (int w = 0; w < 8; w++) s += sh[i][w];
            t[i] = s;
        }
        const float invD = 1.f / (float)DD;
        const float EPSD = 1.1920929e-07f;
#pragma unroll
        for (int g = 0; g < 2; g++) {
            float rk = rsqrtf(t[g] * invD + EPSD);
            float rq = rsqrtf(t[2 + g] * invD + EPSD);
            float gp = t[4 + g] * rk * rq * 0.022097086912079612f;
            float a = sqrtf(fmaxf(fabsf(gp), 1e-6f));
            a = (gp > 0.f) ? a : ((gp < 0.f) ? -a : 0.f);
            float gate = 1.f / (1.f + __expf(-a));
            float inv = rsqrtf(gate * gate * (t[6] * invD) + 1e-5f);
            res[g] = gate;
            res[2 + g] = inv;
        }
    }
    __syncthreads();
    float gate0 = res[0], gate1 = res[1], inv0 = res[2], inv1 = res[3];

    float4* V4 = (float4*)g_value + (size_t)m * (GD / 4);
    float4* X4 = (float4*)g_xnorm + (size_t)m * (GD / 4);
#pragma unroll
    for (int g = 0; g < 2; g++) {
        float gate = g ? gate1 : gate0;
        float inv  = g ? inv1 : inv0;
#pragma unroll
        for (int j = 0; j < 2; j++) {
            int f = tid + 256 * j;
            int off = g * 512 + f;
            float4 v = vr[j];
            float4 val = make_float4(gate * v.x, gate * v.y, gate * v.z, gate * v.w);
            float4 sw = sw4[off];
            float4 xn = make_float4(val.x * inv * sw.x, val.y * inv * sw.y,
                                    val.z * inv * sw.z, val.w * inv * sw.w);
            V4[off] = val;
            X4[off] = xn;
        }
    }
}

// ---------------- 4) conv + silu + residual + cache (2 channels/thread, 64-l blocks) ----------------
__global__ __launch_bounds__(256)
void conv_kernel(const float* __restrict__ cw, float* __restrict__ out,
                 float* __restrict__ cache) {
    int c2 = blockIdx.x * 256 + threadIdx.x;   // channel pair 0..2047
    int c = c2 * 2;
    int b = blockIdx.z;
    int l0 = blockIdx.y * 64;
    float4 wA = *(const float4*)(cw + c * 4);
    float4 wB = *(const float4*)(cw + c * 4 + 4);
    const size_t base = ((size_t)b * LL) * GD + c;
#pragma unroll
    for (int r = 0; r < 3; r++) {
        int l = l0 + r;
        float2 zz = make_float2(0.f, 0.f);
        float2 x3 = (l - 3 >= 0) ? *(const float2*)(g_xnorm + base + (size_t)(l - 3) * GD) : zz;
        float2 x6 = (l - 6 >= 0) ? *(const float2*)(g_xnorm + base + (size_t)(l - 6) * GD) : zz;
        float2 x9 = (l - 9 >= 0) ? *(const float2*)(g_xnorm + base + (size_t)(l - 9) * GD) : zz;
        for (; l < l0 + 64; l += 3) {
            size_t idx = base + (size_t)l * GD;
            float2 x0 = *(const float2*)(g_xnorm + idx);
            float ya = fmaf(wA.w, x0.x, fmaf(wA.z, x3.x, fmaf(wA.y, x6.x, wA.x * x9.x)));
            float yb = fmaf(wB.w, x0.y, fmaf(wB.z, x3.y, fmaf(wB.y, x6.y, wB.x * x9.y)));
            ya = ya / (1.f + __expf(-ya));
            yb = yb / (1.f + __expf(-yb));
            float2 v = *(const float2*)(g_value + idx);
            float2 o = make_float2(v.x + ya, v.y + yb);
            *(float2*)(out + idx) = o;
            if (l >= LL - PAD) {
                cache[((size_t)b * GD + c) * PAD + (l - (LL - PAD))] = x0.x;
                cache[((size_t)b * GD + c + 1) * PAD + (l - (LL - PAD))] = x0.y;
            }
            x9 = x6; x6 = x3; x3 = x0;
        }
    }
}

// ---------------- launcher ----------------
extern "C" void kernel_launch(void* const* d_in, const int* in_sizes, int n_in,
                              void* d_out, int out_size) {
    const float* hs    = (const float*)d_in[0];
    const int*   ids   = (const int*)d_in[1];
    const float* table = (const float*)d_in[2];
    const float* Wk    = (const float*)d_in[3];
    const float* bk    = (const float*)d_in[4];
    const float* Wv    = (const float*)d_in[5];
    const float* bv    = (const float*)d_in[6];
    const float* n1w   = (const float*)d_in[7];
    const float* n2w   = (const float*)d_in[8];
    const float* cw    = (const float*)d_in[9];
    const float* scw   = (const float*)d_in[10];
    float* out   = (float*)d_out;
    float* cache = out + (size_t)MM * GD;

    cudaFuncSetAttribute(gemm_mma_kernel,
                         cudaFuncAttributeMaxDynamicSharedMemorySize, SMEM_TOTAL);

    gather_kernel<<<MM, 256>>>(ids, table);
    wprep_kernel<<<NC, 256>>>(Wk, Wv);
    dim3 ggrid(NC / 128, MM / 128);
    gemm_mma_kernel<<<ggrid, 128, SMEM_TOTAL>>>();
    gate_kernel<<<MM, 256>>>(hs, bk, bv, n1w, n2w, scw);
    dim3 cgrid(GD / 512, LL / 64, BB);
    conv_kernel<<<cgrid, 256>>>(cw, out, cache);
}

// round 7
// speedup vs baseline: 3.7444x; 1.0837x over previous
#include <cuda_runtime.h>
#include <cuda_fp16.h>
#include <math.h>
#include <stdint.h>

// Problem constants
#define BB 4
#define LL 2048
#define GG 2
#define DD 2048
#define HH 16
#define EE 1024          // H*De
#define NN 32768
#define MM (BB*LL)       // 8192 tokens
#define NC 6144          // G*D + D combined GEMM columns
#define GD (GG*DD)       // 4096
#define PAD 9            // (K-1)*DIL

// GEMM tiling
#define KC 64            // K elems per chunk (128 bytes fp16 per row)
#define NCHUNK 32        // 2 passes (Ahi*Bhi, Alo*Bhi) x 16 chunks of 64
#define BUF_BYTES 32768  // A tile 16KB + B tile 16KB
#define SMEM_TOTAL (3 * BUF_BYTES)   // 98304

// ---------------- scratch (static device globals; no allocation) ----------------
__device__ __half g_Ahi[(size_t)MM * EE];
__device__ __half g_Alo[(size_t)MM * EE];
__device__ __half g_Bhi[(size_t)NC * EE];
__device__ float g_C[(size_t)MM * NC];
__device__ float g_value[(size_t)MM * GD];
__device__ float g_inv[(size_t)MM * GG];     // per (token, group) rms-inv scalar

// ---------------- PTX helpers (plain-sm_103-legal) ----------------
__device__ __forceinline__ uint32_t smem_u32(const void* p) {
    uint32_t a;
    asm("{ .reg .u64 t; cvta.to.shared.u64 t, %1; cvt.u32.u64 %0, t; }" : "=r"(a) : "l"(p));
    return a;
}
__device__ __forceinline__ void cp16(uint32_t dst, const void* src) {
    asm volatile("cp.async.cg.shared.global [%0], [%1], 16;\n" :: "r"(dst), "l"(src));
}
__device__ __forceinline__ void ldsm_x4(uint32_t* r, uint32_t addr) {
    asm volatile("ldmatrix.sync.aligned.m8n8.x4.shared.b16 {%0,%1,%2,%3}, [%4];"
                 : "=r"(r[0]), "=r"(r[1]), "=r"(r[2]), "=r"(r[3]) : "r"(addr));
}
__device__ __forceinline__ void mma_fp16(float* d, const uint32_t* a, const uint32_t* b) {
    asm volatile(
        "mma.sync.aligned.m16n8k16.row.col.f32.f16.f16.f32 "
        "{%0,%1,%2,%3}, {%4,%5,%6,%7}, {%8,%9}, {%0,%1,%2,%3};"
        : "+f"(d[0]), "+f"(d[1]), "+f"(d[2]), "+f"(d[3])
        : "r"(a[0]), "r"(a[1]), "r"(a[2]), "r"(a[3]), "r"(b[0]), "r"(b[1]));
}

// ---------------- 1) gather embeddings (fp32 -> fp16 hi/lo split) ----------------
__device__ __forceinline__ uint32_t pack2h(float a, float b, float* ra, float* rb) {
    __half ha = __float2half_rn(a);
    __half hb = __float2half_rn(b);
    *ra = a - __half2float(ha);
    *rb = b - __half2float(hb);
    return (uint32_t)__half_as_ushort(ha) | ((uint32_t)__half_as_ushort(hb) << 16);
}
__device__ __forceinline__ uint32_t pack2hlo(float a, float b) {
    return (uint32_t)__half_as_ushort(__float2half_rn(a)) |
           ((uint32_t)__half_as_ushort(__float2half_rn(b)) << 16);
}

__global__ void gather_kernel(const int* __restrict__ ids,
                              const float* __restrict__ table) {
    int f = blockIdx.x * blockDim.x + threadIdx.x;   // float4 index, total MM*256
    int m  = f >> 8;
    int e4 = f & 255;
    int h  = e4 >> 4;
    int j  = e4 & 15;
    int row = ids[m * HH + h] + h * NN;
    float4 v = ((const float4*)table)[(size_t)row * 16 + j];
    float rx, ry, rz, rw;
    uint2 hi, lo;
    hi.x = pack2h(v.x, v.y, &rx, &ry);
    hi.y = pack2h(v.z, v.w, &rz, &rw);
    lo.x = pack2hlo(rx, ry);
    lo.y = pack2hlo(rz, rw);
    ((uint2*)g_Ahi)[(size_t)m * 256 + e4] = hi;
    ((uint2*)g_Alo)[(size_t)m * 256 + e4] = lo;
}

// ---------------- 1b) weight prep: Wk||Wv -> fp16 hi only ----------------
__global__ void wprep_kernel(const float* __restrict__ Wk, const float* __restrict__ Wv) {
    int f = blockIdx.x * blockDim.x + threadIdx.x;   // float4 idx, total NC*256
    int n = f >> 8;
    int j = f & 255;
    float4 v = (n < GD) ? ((const float4*)Wk)[(size_t)n * 256 + j]
                        : ((const float4*)Wv)[(size_t)(n - GD) * 256 + j];
    uint2 hi;
    hi.x = pack2hlo(v.x, v.y);
    hi.y = pack2hlo(v.z, v.w);
    ((uint2*)g_Bhi)[(size_t)n * 256 + j] = hi;
}

// ---------------- 2) mma.sync fp16 split GEMM ----------------
// C = Ahi*Bhi + Alo*Bhi (fp32 accumulate). Block 128x128, KC=64,
// 3-stage cp.async pipeline, fragment double-buffering, 4 warps (64x64 each).
__global__ __launch_bounds__(128, 2)
void gemm_mma_kernel() {
    extern __shared__ char smem[];
    uint32_t sbase = smem_u32(smem);
    int tid = threadIdx.x;
    int lane = tid & 31;
    int wid = tid >> 5;
    int m0 = blockIdx.y * 128;
    int n0 = blockIdx.x * 128;
    int m_w = (wid & 1) * 64;
    int n_w = (wid >> 1) * 64;

    auto issue_loads = [&](int c, int s) {
        int p = c >> 4;                 // 0 -> Ahi, 1 -> Alo
        int kk = (c & 15) * KC;
        const __half* As = p ? g_Alo : g_Ahi;
        const char* asrc = (const char*)(As + (size_t)(m0 + tid) * EE + kk);
        const char* bsrc = (const char*)(g_Bhi + (size_t)(n0 + tid) * EE + kk);
        uint32_t adst = sbase + s * BUF_BYTES;
        uint32_t bdst = adst + 16384;
#pragma unroll
        for (int q = 0; q < 8; q++) {
            uint32_t off = (uint32_t)tid * 128 + q * 16;
            uint32_t sw = off ^ ((off >> 3) & 0x70);
            cp16(adst + sw, asrc + q * 16);
            cp16(bdst + sw, bsrc + q * 16);
        }
        asm volatile("cp.async.commit_group;\n" ::);
    };

    issue_loads(0, 0);
    issue_loads(1, 1);

    float acc[4][8][4];
#pragma unroll
    for (int i = 0; i < 4; i++)
#pragma unroll
        for (int j = 0; j < 8; j++)
#pragma unroll
            for (int k = 0; k < 4; k++) acc[i][j][k] = 0.f;

    uint32_t arow[4], brow[4];
    uint32_t axorv = (uint32_t)((lane & 7) << 4);
    uint32_t ach = (uint32_t)((lane >> 4) * 16);
#pragma unroll
    for (int mt = 0; mt < 4; mt++)
        arow[mt] = (uint32_t)(m_w + mt * 16 + (lane & 15)) * 128;
    uint32_t bch = (uint32_t)(((lane >> 3) & 1) * 16);
#pragma unroll
    for (int nt = 0; nt < 4; nt++)
        brow[nt] = (uint32_t)(n_w + nt * 16 + ((lane >> 4) & 1) * 8 + (lane & 7)) * 128;

    uint32_t af[2][4][4], bf[2][4][4];

    for (int i = 0; i < NCHUNK; i++) {
        int s = i % 3;
        if (i < NCHUNK - 1) asm volatile("cp.async.wait_group 1;\n" ::);
        else                asm volatile("cp.async.wait_group 0;\n" ::);
        __syncthreads();
        if (i + 2 < NCHUNK) issue_loads(i + 2, (i + 2) % 3);

        uint32_t aBase = sbase + s * BUF_BYTES;
        uint32_t bBase = aBase + 16384;

#pragma unroll
        for (int mt = 0; mt < 4; mt++)
            ldsm_x4(af[0][mt], aBase + arow[mt] + (ach ^ axorv));
#pragma unroll
        for (int nt = 0; nt < 4; nt++)
            ldsm_x4(bf[0][nt], bBase + brow[nt] + (bch ^ axorv));

#pragma unroll
        for (int ks = 0; ks < 4; ks++) {
            int cur = ks & 1, nxt = cur ^ 1;
            if (ks < 3) {
                uint32_t ko = (uint32_t)((ks + 1) * 32);
#pragma unroll
                for (int mt = 0; mt < 4; mt++)
                    ldsm_x4(af[nxt][mt], aBase + arow[mt] + ((ko + ach) ^ axorv));
#pragma unroll
                for (int nt = 0; nt < 4; nt++)
                    ldsm_x4(bf[nxt][nt], bBase + brow[nt] + ((ko + bch) ^ axorv));
            }
#pragma unroll
            for (int mt = 0; mt < 4; mt++)
#pragma unroll
                for (int j = 0; j < 8; j++)
                    mma_fp16(acc[mt][j], af[cur][mt], &bf[cur][j >> 1][(j & 1) * 2]);
        }
    }

    int grp = lane >> 2;
    int qd  = lane & 3;
#pragma unroll
    for (int mt = 0; mt < 4; mt++) {
        int row = m0 + m_w + mt * 16 + grp;
#pragma unroll
        for (int j = 0; j < 8; j++) {
            int col = n0 + n_w + j * 8 + qd * 2;
            *(float2*)(g_C + (size_t)row * NC + col) =
                make_float2(acc[mt][j][0], acc[mt][j][1]);
            *(float2*)(g_C + (size_t)(row + 8) * NC + col) =
                make_float2(acc[mt][j][2], acc[mt][j][3]);
        }
    }
}

// ---------------- 3) fused gate + value (writes value + per-group inv scalar) ----------------
__inline__ __device__ float warpSum(float v) {
#pragma unroll
    for (int o = 16; o; o >>= 1) v += __shfl_xor_sync(0xffffffffu, v, o);
    return v;
}

__global__ __launch_bounds__(256)
void gate_kernel(const float* __restrict__ hs,
                 const float* __restrict__ bk, const float* __restrict__ bv,
                 const float* __restrict__ n1w, const float* __restrict__ n2w) {
    int m = blockIdx.x;
    int tid = threadIdx.x;
    const float4* hs4 = (const float4*)hs + (size_t)m * (GD / 4);
    const float4* C4  = (const float4*)g_C + (size_t)m * (NC / 4);
    const float4* bk4 = (const float4*)bk;
    const float4* bv4 = (const float4*)bv;
    const float4* w14 = (const float4*)n1w;
    const float4* w24 = (const float4*)n2w;

    float sk0 = 0, sk1 = 0, sq0 = 0, sq1 = 0, sp0 = 0, sp1 = 0, sv = 0;
    float4 vr[2];
#pragma unroll
    for (int j = 0; j < 2; j++) {
        int f = tid + 256 * j;
        float4 v = C4[1024 + f];
        float4 bb = bv4[f];
        v.x += bb.x; v.y += bb.y; v.z += bb.z; v.w += bb.w;
        vr[j] = v;
        sv += v.x * v.x + v.y * v.y + v.z * v.z + v.w * v.w;
    }
#pragma unroll
    for (int g = 0; g < 2; g++) {
#pragma unroll
        for (int j = 0; j < 2; j++) {
            int f = tid + 256 * j;
            int off = g * 512 + f;
            float4 kp = C4[off];
            float4 kb = bk4[off];
            kp.x += kb.x; kp.y += kb.y; kp.z += kb.z; kp.w += kb.w;
            float4 q = hs4[off];
            float4 w1 = w14[off];
            float4 w2 = w24[off];
            float skk = kp.x * kp.x + kp.y * kp.y + kp.z * kp.z + kp.w * kp.w;
            float sqq = q.x * q.x + q.y * q.y + q.z * q.z + q.w * q.w;
            float spp = kp.x * q.x * w1.x * w2.x + kp.y * q.y * w1.y * w2.y +
                        kp.z * q.z * w1.z * w2.z + kp.w * q.w * w1.w * w2.w;
            if (g == 0) { sk0 += skk; sq0 += sqq; sp0 += spp; }
            else        { sk1 += skk; sq1 += sqq; sp1 += spp; }
        }
    }

    float vals[7] = { sk0, sk1, sq0, sq1, sp0, sp1, sv };
    __shared__ float sh[7][8];
    __shared__ float res[2];     // gate0, gate1
    int lane = tid & 31, wid = tid >> 5;
#pragma unroll
    for (int i = 0; i < 7; i++) {
        vals[i] = warpSum(vals[i]);
        if (lane == 0) sh[i][wid] = vals[i];
    }
    __syncthreads();
    if (tid == 0) {
        float t[7];
#pragma unroll
        for (int i = 0; i < 7; i++) {
            float s = 0.f;
#pragma unroll
            for (int w = 0; w < 8; w++) s += sh[i][w];
            t[i] = s;
        }
        const float invD = 1.f / (float)DD;
        const float EPSD = 1.1920929e-07f;
#pragma unroll
        for (int g = 0; g < 2; g++) {
            float rk = rsqrtf(t[g] * invD + EPSD);
            float rq = rsqrtf(t[2 + g] * invD + EPSD);
            float gp = t[4 + g] * rk * rq * 0.022097086912079612f;
            float a = sqrtf(fmaxf(fabsf(gp), 1e-6f));
            a = (gp > 0.f) ? a : ((gp < 0.f) ? -a : 0.f);
            float gate = 1.f / (1.f + __expf(-a));
            float inv = rsqrtf(gate * gate * (t[6] * invD) + 1e-5f);
            res[g] = gate;
            g_inv[(size_t)m * GG + g] = inv;       // conv recomputes x_norm from this
        }
    }
    __syncthreads();
    float gate0 = res[0], gate1 = res[1];

    float4* V4 = (float4*)g_value + (size_t)m * (GD / 4);
#pragma unroll
    for (int g = 0; g < 2; g++) {
        float gate = g ? gate1 : gate0;
#pragma unroll
        for (int j = 0; j < 2; j++) {
            int f = tid + 256 * j;
            int off = g * 512 + f;
            float4 v = vr[j];
            V4[off] = make_float4(gate * v.x, gate * v.y, gate * v.z, gate * v.w);
        }
    }
}

// ---------------- 4) conv + silu + residual + cache ----------------
// x_norm recomputed on the fly: xn[l] = value[l] * inv[b,l,g] * sc_w[c].
// 4 channels/thread (float4), rolling 3-residue history.
__global__ __launch_bounds__(256)
void conv_kernel(const float* __restrict__ cw, const float* __restrict__ scw,
                 float* __restrict__ out, float* __restrict__ cache) {
    int c = (blockIdx.x * 256 + threadIdx.x) * 4;   // channel 0..4092, step 4
    int b = blockIdx.z;
    int l0 = blockIdx.y * 64;
    int g = c >> 11;                                 // group (same for all 4 lanes)
    float4 w0 = *(const float4*)(cw + (size_t)c * 4);
    float4 w1 = *(const float4*)(cw + (size_t)c * 4 + 4);
    float4 w2 = *(const float4*)(cw + (size_t)c * 4 + 8);
    float4 w3 = *(const float4*)(cw + (size_t)c * 4 + 12);
    float4 sc = *(const float4*)(scw + c);
    const size_t base = ((size_t)b * LL) * GD + c;
    const float* invp = g_inv + (size_t)b * LL * GG + g;

    auto loadxn = [&](int l) -> float4 {
        if (l < 0) return make_float4(0.f, 0.f, 0.f, 0.f);
        float4 v = *(const float4*)(g_value + base + (size_t)l * GD);
        float iv = invp[(size_t)l * GG];
        return make_float4(v.x * iv * sc.x, v.y * iv * sc.y,
                           v.z * iv * sc.z, v.w * iv * sc.w);
    };

#pragma unroll
    for (int r = 0; r < 3; r++) {
        int l = l0 + r;
        float4 x3 = loadxn(l - 3);
        float4 x6 = loadxn(l - 6);
        float4 x9 = loadxn(l - 9);
        for (; l < l0 + 64; l += 3) {
            size_t idx = base + (size_t)l * GD;
            float4 v = *(const float4*)(g_value + idx);
            float iv = invp[(size_t)l * GG];
            float4 x0 = make_float4(v.x * iv * sc.x, v.y * iv * sc.y,
                                    v.z * iv * sc.z, v.w * iv * sc.w);
            // taps: w[0]*x(l-9) + w[1]*x(l-6) + w[2]*x(l-3) + w[3]*x(l)
            float ya = fmaf(w0.w, x0.x, fmaf(w0.z, x3.x, fmaf(w0.y, x6.x, w0.x * x9.x)));
            float yb = fmaf(w1.w, x0.y, fmaf(w1.z, x3.y, fmaf(w1.y, x6.y, w1.x * x9.y)));
            float yc = fmaf(w2.w, x0.z, fmaf(w2.z, x3.z, fmaf(w2.y, x6.z, w2.x * x9.z)));
            float yd = fmaf(w3.w, x0.w, fmaf(w3.z, x3.w, fmaf(w3.y, x6.w, w3.x * x9.w)));
            ya = ya / (1.f + __expf(-ya));
            yb = yb / (1.f + __expf(-yb));
            yc = yc / (1.f + __expf(-yc));
            yd = yd / (1.f + __expf(-yd));
            *(float4*)(out + idx) = make_float4(v.x + ya, v.y + yb, v.z + yc, v.w + yd);
            if (l >= LL - PAD) {
                int t = l - (LL - PAD);
                cache[((size_t)b * GD + c + 0) * PAD + t] = x0.x;
                cache[((size_t)b * GD + c + 1) * PAD + t] = x0.y;
                cache[((size_t)b * GD + c + 2) * PAD + t] = x0.z;
                cache[((size_t)b * GD + c + 3) * PAD + t] = x0.w;
            }
            x9 = x6; x6 = x3; x3 = x0;
        }
    }
}

// ---------------- launcher ----------------
extern "C" void kernel_launch(void* const* d_in, const int* in_sizes, int n_in,
                              void* d_out, int out_size) {
    const float* hs    = (const float*)d_in[0];
    const int*   ids   = (const int*)d_in[1];
    const float* table = (const float*)d_in[2];
    const float* Wk    = (const float*)d_in[3];
    const float* bk    = (const float*)d_in[4];
    const float* Wv    = (const float*)d_in[5];
    const float* bv    = (const float*)d_in[6];
    const float* n1w   = (const float*)d_in[7];
    const float* n2w   = (const float*)d_in[8];
    const float* cw    = (const float*)d_in[9];
    const float* scw   = (const float*)d_in[10];
    float* out   = (float*)d_out;
    float* cache = out + (size_t)MM * GD;

    cudaFuncSetAttribute(gemm_mma_kernel,
                         cudaFuncAttributeMaxDynamicSharedMemorySize, SMEM_TOTAL);

    gather_kernel<<<MM, 256>>>(ids, table);
    wprep_kernel<<<NC, 256>>>(Wk, Wv);
    dim3 ggrid(NC / 128, MM / 128);
    gemm_mma_kernel<<<ggrid, 128, SMEM_TOTAL>>>();
    gate_kernel<<<MM, 256>>>(hs, bk, bv, n1w, n2w);
    dim3 cgrid(GD / 1024, LL / 64, BB);
    conv_kernel<<<cgrid, 256>>>(cw, scw, out, cache);
}

// round 8
// speedup vs baseline: 6.3485x; 1.6955x over previous
#include <cuda_runtime.h>
#include <cuda_fp16.h>
#include <math.h>
#include <stdint.h>

// Problem constants
#define BB 4
#define LL 2048
#define GG 2
#define DD 2048
#define HH 16
#define EE 1024          // H*De
#define NN 32768
#define MM (BB*LL)       // 8192 tokens
#define NC 6144          // G*D + D combined GEMM columns
#define GD (GG*DD)       // 4096
#define PAD 9            // (K-1)*DIL

// GEMM tiling
#define KC 64            // K elems per chunk (128 bytes fp16 per row)
#define NCHUNK 16        // single fp16 pass: 16 chunks of 64 = K 1024
#define BUF_BYTES 32768  // A tile 16KB + B tile 16KB
#define SMEM_TOTAL (3 * BUF_BYTES)   // 98304

// ---------------- scratch (static device globals; no allocation) ----------------
__device__ __half g_Ahi[(size_t)MM * EE];
__device__ __half g_Bhi[(size_t)NC * EE];
__device__ float g_C[(size_t)MM * NC];
__device__ float g_value[(size_t)MM * GD];
__device__ float g_inv[(size_t)MM * GG];     // per (token, group) rms-inv scalar

// ---------------- PTX helpers (plain-sm_103-legal) ----------------
__device__ __forceinline__ uint32_t smem_u32(const void* p) {
    uint32_t a;
    asm("{ .reg .u64 t; cvta.to.shared.u64 t, %1; cvt.u32.u64 %0, t; }" : "=r"(a) : "l"(p));
    return a;
}
__device__ __forceinline__ void cp16(uint32_t dst, const void* src) {
    asm volatile("cp.async.cg.shared.global [%0], [%1], 16;\n" :: "r"(dst), "l"(src));
}
__device__ __forceinline__ void ldsm_x4(uint32_t* r, uint32_t addr) {
    asm volatile("ldmatrix.sync.aligned.m8n8.x4.shared.b16 {%0,%1,%2,%3}, [%4];"
                 : "=r"(r[0]), "=r"(r[1]), "=r"(r[2]), "=r"(r[3]) : "r"(addr));
}
__device__ __forceinline__ void mma_fp16(float* d, const uint32_t* a, const uint32_t* b) {
    asm volatile(
        "mma.sync.aligned.m16n8k16.row.col.f32.f16.f16.f32 "
        "{%0,%1,%2,%3}, {%4,%5,%6,%7}, {%8,%9}, {%0,%1,%2,%3};"
        : "+f"(d[0]), "+f"(d[1]), "+f"(d[2]), "+f"(d[3])
        : "r"(a[0]), "r"(a[1]), "r"(a[2]), "r"(a[3]), "r"(b[0]), "r"(b[1]));
}

__device__ __forceinline__ uint32_t pack2h(float a, float b) {
    return (uint32_t)__half_as_ushort(__float2half_rn(a)) |
           ((uint32_t)__half_as_ushort(__float2half_rn(b)) << 16);
}

// ---------------- 1) gather embeddings (fp32 -> fp16) ----------------
__global__ void gather_kernel(const int* __restrict__ ids,
                              const float* __restrict__ table) {
    int f = blockIdx.x * blockDim.x + threadIdx.x;   // float4 index, total MM*256
    int m  = f >> 8;
    int e4 = f & 255;
    int h  = e4 >> 4;
    int j  = e4 & 15;
    int row = ids[m * HH + h] + h * NN;
    float4 v = ((const float4*)table)[(size_t)row * 16 + j];
    uint2 hi;
    hi.x = pack2h(v.x, v.y);
    hi.y = pack2h(v.z, v.w);
    ((uint2*)g_Ahi)[(size_t)m * 256 + e4] = hi;
}

// ---------------- 1b) weight prep: Wk||Wv -> fp16 ----------------
__global__ void wprep_kernel(const float* __restrict__ Wk, const float* __restrict__ Wv) {
    int f = blockIdx.x * blockDim.x + threadIdx.x;   // float4 idx, total NC*256
    int n = f >> 8;
    int j = f & 255;
    float4 v = (n < GD) ? ((const float4*)Wk)[(size_t)n * 256 + j]
                        : ((const float4*)Wv)[(size_t)(n - GD) * 256 + j];
    uint2 hi;
    hi.x = pack2h(v.x, v.y);
    hi.y = pack2h(v.z, v.w);
    ((uint2*)g_Bhi)[(size_t)n * 256 + j] = hi;
}

// ---------------- 2) mma.sync fp16 GEMM (single pass) ----------------
// Block 128x128, KC=64, 3-stage cp.async pipeline, fragment double-buffering,
// 4 warps (64x64 each).
__global__ __launch_bounds__(128, 2)
void gemm_mma_kernel() {
    extern __shared__ char smem[];
    uint32_t sbase = smem_u32(smem);
    int tid = threadIdx.x;
    int lane = tid & 31;
    int wid = tid >> 5;
    int m0 = blockIdx.y * 128;
    int n0 = blockIdx.x * 128;
    int m_w = (wid & 1) * 64;
    int n_w = (wid >> 1) * 64;

    auto issue_loads = [&](int c, int s) {
        int kk = c * KC;
        const char* asrc = (const char*)(g_Ahi + (size_t)(m0 + tid) * EE + kk);
        const char* bsrc = (const char*)(g_Bhi + (size_t)(n0 + tid) * EE + kk);
        uint32_t adst = sbase + s * BUF_BYTES;
        uint32_t bdst = adst + 16384;
#pragma unroll
        for (int q = 0; q < 8; q++) {
            uint32_t off = (uint32_t)tid * 128 + q * 16;
            uint32_t sw = off ^ ((off >> 3) & 0x70);
            cp16(adst + sw, asrc + q * 16);
            cp16(bdst + sw, bsrc + q * 16);
        }
        asm volatile("cp.async.commit_group;\n" ::);
    };

    issue_loads(0, 0);
    issue_loads(1, 1);

    float acc[4][8][4];
#pragma unroll
    for (int i = 0; i < 4; i++)
#pragma unroll
        for (int j = 0; j < 8; j++)
#pragma unroll
            for (int k = 0; k < 4; k++) acc[i][j][k] = 0.f;

    uint32_t arow[4], brow[4];
    uint32_t axorv = (uint32_t)((lane & 7) << 4);
    uint32_t ach = (uint32_t)((lane >> 4) * 16);
#pragma unroll
    for (int mt = 0; mt < 4; mt++)
        arow[mt] = (uint32_t)(m_w + mt * 16 + (lane & 15)) * 128;
    uint32_t bch = (uint32_t)(((lane >> 3) & 1) * 16);
#pragma unroll
    for (int nt = 0; nt < 4; nt++)
        brow[nt] = (uint32_t)(n_w + nt * 16 + ((lane >> 4) & 1) * 8 + (lane & 7)) * 128;

    uint32_t af[2][4][4], bf[2][4][4];

    for (int i = 0; i < NCHUNK; i++) {
        int s = i % 3;
        if (i < NCHUNK - 1) asm volatile("cp.async.wait_group 1;\n" ::);
        else                asm volatile("cp.async.wait_group 0;\n" ::);
        __syncthreads();
        if (i + 2 < NCHUNK) issue_loads(i + 2, (i + 2) % 3);

        uint32_t aBase = sbase + s * BUF_BYTES;
        uint32_t bBase = aBase + 16384;

#pragma unroll
        for (int mt = 0; mt < 4; mt++)
            ldsm_x4(af[0][mt], aBase + arow[mt] + (ach ^ axorv));
#pragma unroll
        for (int nt = 0; nt < 4; nt++)
            ldsm_x4(bf[0][nt], bBase + brow[nt] + (bch ^ axorv));

#pragma unroll
        for (int ks = 0; ks < 4; ks++) {
            int cur = ks & 1, nxt = cur ^ 1;
            if (ks < 3) {
                uint32_t ko = (uint32_t)((ks + 1) * 32);
#pragma unroll
                for (int mt = 0; mt < 4; mt++)
                    ldsm_x4(af[nxt][mt], aBase + arow[mt] + ((ko + ach) ^ axorv));
#pragma unroll
                for (int nt = 0; nt < 4; nt++)
                    ldsm_x4(bf[nxt][nt], bBase + brow[nt] + ((ko + bch) ^ axorv));
            }
#pragma unroll
            for (int mt = 0; mt < 4; mt++)
#pragma unroll
                for (int j = 0; j < 8; j++)
                    mma_fp16(acc[mt][j], af[cur][mt], &bf[cur][j >> 1][(j & 1) * 2]);
        }
    }

    int grp = lane >> 2;
    int qd  = lane & 3;
#pragma unroll
    for (int mt = 0; mt < 4; mt++) {
        int row = m0 + m_w + mt * 16 + grp;
#pragma unroll
        for (int j = 0; j < 8; j++) {
            int col = n0 + n_w + j * 8 + qd * 2;
            *(float2*)(g_C + (size_t)row * NC + col) =
                make_float2(acc[mt][j][0], acc[mt][j][1]);
            *(float2*)(g_C + (size_t)(row + 8) * NC + col) =
                make_float2(acc[mt][j][2], acc[mt][j][3]);
        }
    }
}

// ---------------- 3) fused gate + value (writes value + per-group inv scalar) ----------------
__inline__ __device__ float warpSum(float v) {
#pragma unroll
    for (int o = 16; o; o >>= 1) v += __shfl_xor_sync(0xffffffffu, v, o);
    return v;
}

__global__ __launch_bounds__(256)
void gate_kernel(const float* __restrict__ hs,
                 const float* __restrict__ bk, const float* __restrict__ bv,
                 const float* __restrict__ n1w, const float* __restrict__ n2w) {
    int m = blockIdx.x;
    int tid = threadIdx.x;
    const float4* hs4 = (const float4*)hs + (size_t)m * (GD / 4);
    const float4* C4  = (const float4*)g_C + (size_t)m * (NC / 4);
    const float4* bk4 = (const float4*)bk;
    const float4* bv4 = (const float4*)bv;
    const float4* w14 = (const float4*)n1w;
    const float4* w24 = (const float4*)n2w;

    float sk0 = 0, sk1 = 0, sq0 = 0, sq1 = 0, sp0 = 0, sp1 = 0, sv = 0;
    float4 vr[2];
#pragma unroll
    for (int j = 0; j < 2; j++) {
        int f = tid + 256 * j;
        float4 v = C4[1024 + f];
        float4 bb = bv4[f];
        v.x += bb.x; v.y += bb.y; v.z += bb.z; v.w += bb.w;
        vr[j] = v;
        sv += v.x * v.x + v.y * v.y + v.z * v.z + v.w * v.w;
    }
#pragma unroll
    for (int g = 0; g < 2; g++) {
#pragma unroll
        for (int j = 0; j < 2; j++) {
            int f = tid + 256 * j;
            int off = g * 512 + f;
            float4 kp = C4[off];
            float4 kb = bk4[off];
            kp.x += kb.x; kp.y += kb.y; kp.z += kb.z; kp.w += kb.w;
            float4 q = hs4[off];
            float4 w1 = w14[off];
            float4 w2 = w24[off];
            float skk = kp.x * kp.x + kp.y * kp.y + kp.z * kp.z + kp.w * kp.w;
            float sqq = q.x * q.x + q.y * q.y + q.z * q.z + q.w * q.w;
            float spp = kp.x * q.x * w1.x * w2.x + kp.y * q.y * w1.y * w2.y +
                        kp.z * q.z * w1.z * w2.z + kp.w * q.w * w1.w * w2.w;
            if (g == 0) { sk0 += skk; sq0 += sqq; sp0 += spp; }
            else        { sk1 += skk; sq1 += sqq; sp1 += spp; }
        }
    }

    float vals[7] = { sk0, sk1, sq0, sq1, sp0, sp1, sv };
    __shared__ float sh[7][8];
    __shared__ float res[2];     // gate0, gate1
    int lane = tid & 31, wid = tid >> 5;
#pragma unroll
    for (int i = 0; i < 7; i++) {
        vals[i] = warpSum(vals[i]);
        if (lane == 0) sh[i][wid] = vals[i];
    }
    __syncthreads();
    if (tid == 0) {
        float t[7];
#pragma unroll
        for (int i = 0; i < 7; i++) {
            float s = 0.f;
#pragma unroll
            for (int w = 0; w < 8; w++) s += sh[i][w];
            t[i] = s;
        }
        const float invD = 1.f / (float)DD;
        const float EPSD = 1.1920929e-07f;
#pragma unroll
        for (int g = 0; g < 2; g++) {
            float rk = rsqrtf(t[g] * invD + EPSD);
            float rq = rsqrtf(t[2 + g] * invD + EPSD);
            float gp = t[4 + g] * rk * rq * 0.022097086912079612f;
            float a = sqrtf(fmaxf(fabsf(gp), 1e-6f));
            a = (gp > 0.f) ? a : ((gp < 0.f) ? -a : 0.f);
            float gate = 1.f / (1.f + __expf(-a));
            float inv = rsqrtf(gate * gate * (t[6] * invD) + 1e-5f);
            res[g] = gate;
            g_inv[(size_t)m * GG + g] = inv;       // conv recomputes x_norm from this
        }
    }
    __syncthreads();
    float gate0 = res[0], gate1 = res[1];

    float4* V4 = (float4*)g_value + (size_t)m * (GD / 4);
#pragma unroll
    for (int g = 0; g < 2; g++) {
        float gate = g ? gate1 : gate0;
#pragma unroll
        for (int j = 0; j < 2; j++) {
            int f = tid + 256 * j;
            int off = g * 512 + f;
            float4 v = vr[j];
            V4[off] = make_float4(gate * v.x, gate * v.y, gate * v.z, gate * v.w);
        }
    }
}

// ---------------- 4) conv + silu + residual + cache ----------------
// x_norm recomputed on the fly: xn[l] = value[l] * inv[b,l,g] * sc_w[c].
// 4 channels/thread (float4), rolling 3-residue history.
__global__ __launch_bounds__(256)
void conv_kernel(const float* __restrict__ cw, const float* __restrict__ scw,
                 float* __restrict__ out, float* __restrict__ cache) {
    int c = (blockIdx.x * 256 + threadIdx.x) * 4;   // channel 0..4092, step 4
    int b = blockIdx.z;
    int l0 = blockIdx.y * 64;
    int g = c >> 11;                                 // group (same for all 4 lanes)
    float4 w0 = *(const float4*)(cw + (size_t)c * 4);
    float4 w1 = *(const float4*)(cw + (size_t)c * 4 + 4);
    float4 w2 = *(const float4*)(cw + (size_t)c * 4 + 8);
    float4 w3 = *(const float4*)(cw + (size_t)c * 4 + 12);
    float4 sc = *(const float4*)(scw + c);
    const size_t base = ((size_t)b * LL) * GD + c;
    const float* invp = g_inv + (size_t)b * LL * GG + g;

    auto loadxn = [&](int l) -> float4 {
        if (l < 0) return make_float4(0.f, 0.f, 0.f, 0.f);
        float4 v = *(const float4*)(g_value + base + (size_t)l * GD);
        float iv = invp[(size_t)l * GG];
        return make_float4(v.x * iv * sc.x, v.y * iv * sc.y,
                           v.z * iv * sc.z, v.w * iv * sc.w);
    };

#pragma unroll
    for (int r = 0; r < 3; r++) {
        int l = l0 + r;
        float4 x3 = loadxn(l - 3);
        float4 x6 = loadxn(l - 6);
        float4 x9 = loadxn(l - 9);
        for (; l < l0 + 64; l += 3) {
            size_t idx = base + (size_t)l * GD;
            float4 v = *(const float4*)(g_value + idx);
            float iv = invp[(size_t)l * GG];
            float4 x0 = make_float4(v.x * iv * sc.x, v.y * iv * sc.y,
                                    v.z * iv * sc.z, v.w * iv * sc.w);
            float ya = fmaf(w0.w, x0.x, fmaf(w0.z, x3.x, fmaf(w0.y, x6.x, w0.x * x9.x)));
            float yb = fmaf(w1.w, x0.y, fmaf(w1.z, x3.y, fmaf(w1.y, x6.y, w1.x * x9.y)));
            float yc = fmaf(w2.w, x0.z, fmaf(w2.z, x3.z, fmaf(w2.y, x6.z, w2.x * x9.z)));
            float yd = fmaf(w3.w, x0.w, fmaf(w3.z, x3.w, fmaf(w3.y, x6.w, w3.x * x9.w)));
            ya = ya / (1.f + __expf(-ya));
            yb = yb / (1.f + __expf(-yb));
            yc = yc / (1.f + __expf(-yc));
            yd = yd / (1.f + __expf(-yd));
            *(float4*)(out + idx) = make_float4(v.x + ya, v.y + yb, v.z + yc, v.w + yd);
            if (l >= LL - PAD) {
                int t = l - (LL - PAD);
                cache[((size_t)b * GD + c + 0) * PAD + t] = x0.x;
                cache[((size_t)b * GD + c + 1) * PAD + t] = x0.y;
                cache[((size_t)b * GD + c + 2) * PAD + t] = x0.z;
                cache[((size_t)b * GD + c + 3) * PAD + t] = x0.w;
            }
            x9 = x6; x6 = x3; x3 = x0;
        }
    }
}

// ---------------- launcher ----------------
extern "C" void kernel_launch(void* const* d_in, const int* in_sizes, int n_in,
                              void* d_out, int out_size) {
    const float* hs    = (const float*)d_in[0];
    const int*   ids   = (const int*)d_in[1];
    const float* table = (const float*)d_in[2];
    const float* Wk    = (const float*)d_in[3];
    const float* bk    = (const float*)d_in[4];
    const float* Wv    = (const float*)d_in[5];
    const float* bv    = (const float*)d_in[6];
    const float* n1w   = (const float*)d_in[7];
    const float* n2w   = (const float*)d_in[8];
    const float* cw    = (const float*)d_in[9];
    const float* scw   = (const float*)d_in[10];
    float* out   = (float*)d_out;
    float* cache = out + (size_t)MM * GD;

    cudaFuncSetAttribute(gemm_mma_kernel,
                         cudaFuncAttributeMaxDynamicSharedMemorySize, SMEM_TOTAL);

    gather_kernel<<<MM, 256>>>(ids, table);
    wprep_kernel<<<NC, 256>>>(Wk, Wv);
    dim3 ggrid(NC / 128, MM / 128);
    gemm_mma_kernel<<<ggrid, 128, SMEM_TOTAL>>>();
    gate_kernel<<<MM, 256>>>(hs, bk, bv, n1w, n2w);
    dim3 cgrid(GD / 1024, LL / 64, BB);
    conv_kernel<<<cgrid, 256>>>(cw, scw, out, cache);
}

// round 9
// speedup vs baseline: 7.0332x; 1.1079x over previous
#include <cuda_runtime.h>
#include <cuda_fp16.h>
#include <math.h>
#include <stdint.h>

// Problem constants
#define BB 4
#define LL 2048
#define GG 2
#define DD 2048
#define HH 16
#define EE 1024          // H*De
#define NN 32768
#define MM (BB*LL)       // 8192 tokens
#define NC 6144          // G*D + D combined GEMM columns
#define GD (GG*DD)       // 4096
#define PAD 9            // (K-1)*DIL

// GEMM tiling
#define KC 64            // K elems per chunk (128 bytes fp16 per row)
#define NCHUNK 16        // single fp16 pass: 16 chunks of 64 = K 1024
#define BUF_BYTES 32768  // A tile 16KB + B tile 16KB
#define SMEM_TOTAL (3 * BUF_BYTES)   // 98304

// ---------------- scratch (static device globals; no allocation) ----------------
__device__ __half g_Ahi[(size_t)MM * EE];
__device__ __half g_Bhi[(size_t)NC * EE];
__device__ float g_vproj[(size_t)MM * DD];   // vproj + bv (only GEMM output stored)
__device__ float g_red[(size_t)MM * 8];      // per token: sk[2], sq[2], sp[2], sv, pad
__device__ float4 g_gi[(size_t)MM];          // per token: gate0, gate1, inv0, inv1

// ---------------- PTX helpers (plain-sm_103-legal) ----------------
__device__ __forceinline__ uint32_t smem_u32(const void* p) {
    uint32_t a;
    asm("{ .reg .u64 t; cvta.to.shared.u64 t, %1; cvt.u32.u64 %0, t; }" : "=r"(a) : "l"(p));
    return a;
}
__device__ __forceinline__ void cp16(uint32_t dst, const void* src) {
    asm volatile("cp.async.cg.shared.global [%0], [%1], 16;\n" :: "r"(dst), "l"(src));
}
__device__ __forceinline__ void ldsm_x4(uint32_t* r, uint32_t addr) {
    asm volatile("ldmatrix.sync.aligned.m8n8.x4.shared.b16 {%0,%1,%2,%3}, [%4];"
                 : "=r"(r[0]), "=r"(r[1]), "=r"(r[2]), "=r"(r[3]) : "r"(addr));
}
__device__ __forceinline__ void mma_fp16(float* d, const uint32_t* a, const uint32_t* b) {
    asm volatile(
        "mma.sync.aligned.m16n8k16.row.col.f32.f16.f16.f32 "
        "{%0,%1,%2,%3}, {%4,%5,%6,%7}, {%8,%9}, {%0,%1,%2,%3};"
        : "+f"(d[0]), "+f"(d[1]), "+f"(d[2]), "+f"(d[3])
        : "r"(a[0]), "r"(a[1]), "r"(a[2]), "r"(a[3]), "r"(b[0]), "r"(b[1]));
}

__device__ __forceinline__ uint32_t pack2h(float a, float b) {
    return (uint32_t)__half_as_ushort(__float2half_rn(a)) |
           ((uint32_t)__half_as_ushort(__float2half_rn(b)) << 16);
}

// ---------------- 1) gather embeddings (fp32 -> fp16) + zero reduction buffer ----------------
__global__ void gather_kernel(const int* __restrict__ ids,
                              const float* __restrict__ table) {
    int m  = blockIdx.x;                 // one block per token
    int e4 = threadIdx.x;                // float4 within 1024-float row
    if (e4 < 8) g_red[(size_t)m * 8 + e4] = 0.f;   // zero per-launch accumulators
    int h  = e4 >> 4;
    int j  = e4 & 15;
    int row = ids[m * HH + h] + h * NN;
    float4 v = ((const float4*)table)[(size_t)row * 16 + j];
    uint2 hi;
    hi.x = pack2h(v.x, v.y);
    hi.y = pack2h(v.z, v.w);
    ((uint2*)g_Ahi)[(size_t)m * 256 + e4] = hi;
}

// ---------------- 1b) weight prep: Wk||Wv -> fp16 ----------------
__global__ void wprep_kernel(const float* __restrict__ Wk, const float* __restrict__ Wv) {
    int f = blockIdx.x * blockDim.x + threadIdx.x;   // float4 idx, total NC*256
    int n = f >> 8;
    int j = f & 255;
    float4 v = (n < GD) ? ((const float4*)Wk)[(size_t)n * 256 + j]
                        : ((const float4*)Wv)[(size_t)(n - GD) * 256 + j];
    uint2 hi;
    hi.x = pack2h(v.x, v.y);
    hi.y = pack2h(v.z, v.w);
    ((uint2*)g_Bhi)[(size_t)n * 256 + j] = hi;
}

// ---------------- 2) mma.sync fp16 GEMM + fused gate-reduction epilogue ----------------
// Block 128x128, KC=64, 3-stage cp.async pipeline, 4 warps (64x64 each).
// keyp tiles (n0<4096): no C store; per-row partials of sk/sq/sp -> atomicAdd g_red.
// vproj tiles: store vproj+bv to g_vproj; per-row sv partials -> atomicAdd.
__global__ __launch_bounds__(128, 2)
void gemm_mma_kernel(const float* __restrict__ hs,
                     const float* __restrict__ bk, const float* __restrict__ bv,
                     const float* __restrict__ n1w, const float* __restrict__ n2w) {
    extern __shared__ char smem[];
    uint32_t sbase = smem_u32(smem);
    int tid = threadIdx.x;
    int lane = tid & 31;
    int wid = tid >> 5;
    int m0 = blockIdx.y * 128;
    int n0 = blockIdx.x * 128;
    int m_w = (wid & 1) * 64;
    int n_w = (wid >> 1) * 64;

    auto issue_loads = [&](int c, int s) {
        int kk = c * KC;
        const char* asrc = (const char*)(g_Ahi + (size_t)(m0 + tid) * EE + kk);
        const char* bsrc = (const char*)(g_Bhi + (size_t)(n0 + tid) * EE + kk);
        uint32_t adst = sbase + s * BUF_BYTES;
        uint32_t bdst = adst + 16384;
#pragma unroll
        for (int q = 0; q < 8; q++) {
            uint32_t off = (uint32_t)tid * 128 + q * 16;
            uint32_t sw = off ^ ((off >> 3) & 0x70);
            cp16(adst + sw, asrc + q * 16);
            cp16(bdst + sw, bsrc + q * 16);
        }
        asm volatile("cp.async.commit_group;\n" ::);
    };

    issue_loads(0, 0);
    issue_loads(1, 1);

    float acc[4][8][4];
#pragma unroll
    for (int i = 0; i < 4; i++)
#pragma unroll
        for (int j = 0; j < 8; j++)
#pragma unroll
            for (int k = 0; k < 4; k++) acc[i][j][k] = 0.f;

    uint32_t arow[4], brow[4];
    uint32_t axorv = (uint32_t)((lane & 7) << 4);
    uint32_t ach = (uint32_t)((lane >> 4) * 16);
#pragma unroll
    for (int mt = 0; mt < 4; mt++)
        arow[mt] = (uint32_t)(m_w + mt * 16 + (lane & 15)) * 128;
    uint32_t bch = (uint32_t)(((lane >> 3) & 1) * 16);
#pragma unroll
    for (int nt = 0; nt < 4; nt++)
        brow[nt] = (uint32_t)(n_w + nt * 16 + ((lane >> 4) & 1) * 8 + (lane & 7)) * 128;

    uint32_t af[2][4][4], bf[2][4][4];

    for (int i = 0; i < NCHUNK; i++) {
        int s = i % 3;
        if (i < NCHUNK - 1) asm volatile("cp.async.wait_group 1;\n" ::);
        else                asm volatile("cp.async.wait_group 0;\n" ::);
        __syncthreads();
        if (i + 2 < NCHUNK) issue_loads(i + 2, (i + 2) % 3);

        uint32_t aBase = sbase + s * BUF_BYTES;
        uint32_t bBase = aBase + 16384;

#pragma unroll
        for (int mt = 0; mt < 4; mt++)
            ldsm_x4(af[0][mt], aBase + arow[mt] + (ach ^ axorv));
#pragma unroll
        for (int nt = 0; nt < 4; nt++)
            ldsm_x4(bf[0][nt], bBase + brow[nt] + (bch ^ axorv));

#pragma unroll
        for (int ks = 0; ks < 4; ks++) {
            int cur = ks & 1, nxt = cur ^ 1;
            if (ks < 3) {
                uint32_t ko = (uint32_t)((ks + 1) * 32);
#pragma unroll
                for (int mt = 0; mt < 4; mt++)
                    ldsm_x4(af[nxt][mt], aBase + arow[mt] + ((ko + ach) ^ axorv));
#pragma unroll
                for (int nt = 0; nt < 4; nt++)
                    ldsm_x4(bf[nxt][nt], bBase + brow[nt] + ((ko + bch) ^ axorv));
            }
#pragma unroll
            for (int mt = 0; mt < 4; mt++)
#pragma unroll
                for (int j = 0; j < 8; j++)
                    mma_fp16(acc[mt][j], af[cur][mt], &bf[cur][j >> 1][(j & 1) * 2]);
        }
    }

    // ---- fused epilogue ----
    int grp = lane >> 2;
    int qd  = lane & 3;
    if (n0 < GD) {
        // keyp tile: per-row partial sums, no C store
        int g = n0 >> 11;
        float2 bkv[8], wwv[8];
#pragma unroll
        for (int j = 0; j < 8; j++) {
            int col = n0 + n_w + j * 8 + qd * 2;
            bkv[j] = *(const float2*)(bk + col);
            float2 a1 = *(const float2*)(n1w + col);
            float2 a2 = *(const float2*)(n2w + col);
            wwv[j] = make_float2(a1.x * a2.x, a1.y * a2.y);
        }
#pragma unroll
        for (int mt = 0; mt < 4; mt++) {
            int r0 = m0 + m_w + mt * 16 + grp;
            int r1 = r0 + 8;
            const float* h0 = hs + (size_t)r0 * GD + n0 + n_w + qd * 2;
            const float* h1 = hs + (size_t)r1 * GD + n0 + n_w + qd * 2;
            float sk0 = 0, sq0 = 0, sp0 = 0, sk1 = 0, sq1 = 0, sp1 = 0;
#pragma unroll
            for (int j = 0; j < 8; j++) {
                float2 q0 = *(const float2*)(h0 + j * 8);
                float2 q1 = *(const float2*)(h1 + j * 8);
                float kx = acc[mt][j][0] + bkv[j].x;
                float ky = acc[mt][j][1] + bkv[j].y;
                sk0 += kx * kx + ky * ky;
                sq0 += q0.x * q0.x + q0.y * q0.y;
                sp0 += kx * q0.x * wwv[j].x + ky * q0.y * wwv[j].y;
                kx = acc[mt][j][2] + bkv[j].x;
                ky = acc[mt][j][3] + bkv[j].y;
                sk1 += kx * kx + ky * ky;
                sq1 += q1.x * q1.x + q1.y * q1.y;
                sp1 += kx * q1.x * wwv[j].x + ky * q1.y * wwv[j].y;
            }
#pragma unroll
            for (int o = 1; o <= 2; o <<= 1) {
                sk0 += __shfl_xor_sync(0xffffffffu, sk0, o);
                sq0 += __shfl_xor_sync(0xffffffffu, sq0, o);
                sp0 += __shfl_xor_sync(0xffffffffu, sp0, o);
                sk1 += __shfl_xor_sync(0xffffffffu, sk1, o);
                sq1 += __shfl_xor_sync(0xffffffffu, sq1, o);
                sp1 += __shfl_xor_sync(0xffffffffu, sp1, o);
            }
            if (qd == 0) {
                atomicAdd(&g_red[(size_t)r0 * 8 + 0 + g], sk0);
                atomicAdd(&g_red[(size_t)r0 * 8 + 2 + g], sq0);
                atomicAdd(&g_red[(size_t)r0 * 8 + 4 + g], sp0);
                atomicAdd(&g_red[(size_t)r1 * 8 + 0 + g], sk1);
                atomicAdd(&g_red[(size_t)r1 * 8 + 2 + g], sq1);
                atomicAdd(&g_red[(size_t)r1 * 8 + 4 + g], sp1);
            }
        }
    } else {
        // vproj tile: store vproj+bv, accumulate sv
        int dd = n0 - GD + n_w + qd * 2;
        float2 bvv[8];
#pragma unroll
        for (int j = 0; j < 8; j++) bvv[j] = *(const float2*)(bv + dd + j * 8);
#pragma unroll
        for (int mt = 0; mt < 4; mt++) {
            int r0 = m0 + m_w + mt * 16 + grp;
            int r1 = r0 + 8;
            float* vp0 = g_vproj + (size_t)r0 * DD + dd;
            float* vp1 = g_vproj + (size_t)r1 * DD + dd;
            float sv0 = 0, sv1 = 0;
#pragma unroll
            for (int j = 0; j < 8; j++) {
                float vx = acc[mt][j][0] + bvv[j].x;
                float vy = acc[mt][j][1] + bvv[j].y;
                sv0 += vx * vx + vy * vy;
                *(float2*)(vp0 + j * 8) = make_float2(vx, vy);
                vx = acc[mt][j][2] + bvv[j].x;
                vy = acc[mt][j][3] + bvv[j].y;
                sv1 += vx * vx + vy * vy;
                *(float2*)(vp1 + j * 8) = make_float2(vx, vy);
            }
#pragma unroll
            for (int o = 1; o <= 2; o <<= 1) {
                sv0 += __shfl_xor_sync(0xffffffffu, sv0, o);
                sv1 += __shfl_xor_sync(0xffffffffu, sv1, o);
            }
            if (qd == 0) {
                atomicAdd(&g_red[(size_t)r0 * 8 + 6], sv0);
                atomicAdd(&g_red[(size_t)r1 * 8 + 6], sv1);
            }
        }
    }
}

// ---------------- 3) tiny gate/inv kernel ----------------
__global__ void gate2_kernel() {
    int m = blockIdx.x * 256 + threadIdx.x;
    const float invD = 1.f / (float)DD;
    const float EPSD = 1.1920929e-07f;
    float svm = g_red[(size_t)m * 8 + 6] * invD;
    float gates[2], invs[2];
#pragma unroll
    for (int g = 0; g < 2; g++) {
        float sk = g_red[(size_t)m * 8 + 0 + g];
        float sq = g_red[(size_t)m * 8 + 2 + g];
        float sp = g_red[(size_t)m * 8 + 4 + g];
        float rk = rsqrtf(sk * invD + EPSD);
        float rq = rsqrtf(sq * invD + EPSD);
        float gp = sp * rk * rq * 0.022097086912079612f;
        float a = sqrtf(fmaxf(fabsf(gp), 1e-6f));
        a = (gp > 0.f) ? a : ((gp < 0.f) ? -a : 0.f);
        float gate = 1.f / (1.f + __expf(-a));
        gates[g] = gate;
        invs[g] = rsqrtf(gate * gate * svm + 1e-5f);
    }
    g_gi[m] = make_float4(gates[0], gates[1], invs[0], invs[1]);
}

// ---------------- 4) conv + silu + residual + cache ----------------
// value = gate_g * vproj[d]; xn = value * inv * sc_w. 4 channels/thread.
__global__ __launch_bounds__(256)
void conv_kernel(const float* __restrict__ cw, const float* __restrict__ scw,
                 float* __restrict__ out, float* __restrict__ cache) {
    int c = (blockIdx.x * 256 + threadIdx.x) * 4;   // channel 0..4092, step 4
    int b = blockIdx.z;
    int l0 = blockIdx.y * 64;
    int g = c >> 11;
    int d = c & 2047;
    float4 w0 = *(const float4*)(cw + (size_t)c * 4);
    float4 w1 = *(const float4*)(cw + (size_t)c * 4 + 4);
    float4 w2 = *(const float4*)(cw + (size_t)c * 4 + 8);
    float4 w3 = *(const float4*)(cw + (size_t)c * 4 + 12);
    float4 sc = *(const float4*)(scw + c);
    const size_t baseo = ((size_t)b * LL) * GD + c;
    const size_t basev = ((size_t)b * LL) * DD + d;
    const float4* gip = g_gi + (size_t)b * LL;

    auto loadxn = [&](int l) -> float4 {
        if (l < 0) return make_float4(0.f, 0.f, 0.f, 0.f);
        float4 gi = gip[l];
        float s = (g ? gi.y : gi.x) * (g ? gi.w : gi.z);   // gate*inv
        float4 vp = *(const float4*)(g_vproj + basev + (size_t)l * DD);
        return make_float4(vp.x * s * sc.x, vp.y * s * sc.y,
                           vp.z * s * sc.z, vp.w * s * sc.w);
    };

#pragma unroll
    for (int r = 0; r < 3; r++) {
        int l = l0 + r;
        float4 x3 = loadxn(l - 3);
        float4 x6 = loadxn(l - 6);
        float4 x9 = loadxn(l - 9);
        for (; l < l0 + 64; l += 3) {
            float4 gi = gip[l];
            float gate = g ? gi.y : gi.x;
            float iv   = g ? gi.w : gi.z;
            float4 vp = *(const float4*)(g_vproj + basev + (size_t)l * DD);
            float4 v  = make_float4(vp.x * gate, vp.y * gate, vp.z * gate, vp.w * gate);
            float si = iv * 1.f;
            float4 x0 = make_float4(v.x * si * sc.x, v.y * si * sc.y,
                                    v.z * si * sc.z, v.w * si * sc.w);
            float ya = fmaf(w0.w, x0.x, fmaf(w0.z, x3.x, fmaf(w0.y, x6.x, w0.x * x9.x)));
            float yb = fmaf(w1.w, x0.y, fmaf(w1.z, x3.y, fmaf(w1.y, x6.y, w1.x * x9.y)));
            float yc = fmaf(w2.w, x0.z, fmaf(w2.z, x3.z, fmaf(w2.y, x6.z, w2.x * x9.z)));
            float yd = fmaf(w3.w, x0.w, fmaf(w3.z, x3.w, fmaf(w3.y, x6.w, w3.x * x9.w)));
            ya = ya / (1.f + __expf(-ya));
            yb = yb / (1.f + __expf(-yb));
            yc = yc / (1.f + __expf(-yc));
            yd = yd / (1.f + __expf(-yd));
            size_t idx = baseo + (size_t)l * GD;
            *(float4*)(out + idx) = make_float4(v.x + ya, v.y + yb, v.z + yc, v.w + yd);
            if (l >= LL - PAD) {
                int t = l - (LL - PAD);
                cache[((size_t)b * GD + c + 0) * PAD + t] = x0.x;
                cache[((size_t)b * GD + c + 1) * PAD + t] = x0.y;
                cache[((size_t)b * GD + c + 2) * PAD + t] = x0.z;
                cache[((size_t)b * GD + c + 3) * PAD + t] = x0.w;
            }
            x9 = x6; x6 = x3; x3 = x0;
        }
    }
}

// ---------------- launcher ----------------
extern "C" void kernel_launch(void* const* d_in, const int* in_sizes, int n_in,
                              void* d_out, int out_size) {
    const float* hs    = (const float*)d_in[0];
    const int*   ids   = (const int*)d_in[1];
    const float* table = (const float*)d_in[2];
    const float* Wk    = (const float*)d_in[3];
    const float* bk    = (const float*)d_in[4];
    const float* Wv    = (const float*)d_in[5];
    const float* bv    = (const float*)d_in[6];
    const float* n1w   = (const float*)d_in[7];
    const float* n2w   = (const float*)d_in[8];
    const float* cw    = (const float*)d_in[9];
    const float* scw   = (const float*)d_in[10];
    float* out   = (float*)d_out;
    float* cache = out + (size_t)MM * GD;

    cudaFuncSetAttribute(gemm_mma_kernel,
                         cudaFuncAttributeMaxDynamicSharedMemorySize, SMEM_TOTAL);

    gather_kernel<<<MM, 256>>>(ids, table);
    wprep_kernel<<<NC, 256>>>(Wk, Wv);
    dim3 ggrid(NC / 128, MM / 128);
    gemm_mma_kernel<<<ggrid, 128, SMEM_TOTAL>>>(hs, bk, bv, n1w, n2w);
    gate2_kernel<<<MM / 256, 256>>>();
    dim3 cgrid(GD / 1024, LL / 64, BB);
    conv_kernel<<<cgrid, 256>>>(cw, scw, out, cache);
}